// round 1
// baseline (speedup 1.0000x reference)
#include <cuda_runtime.h>
#include <math.h>

// Problem dims
#define BB   2
#define NN   4096
#define DD   640
#define HH   8
#define DHD  80
#define CNN  77
#define CDD  768
#define FFF  2560   // GEGLU inner
#define ROWS (BB*NN)          // 8192
#define CROWS (BB*CNN)        // 154

// ---------------- scratch (device globals; no allocation) ----------------
__device__ float g_h   [ROWS*DD];
__device__ float g_q   [ROWS*DD];
__device__ float g_k   [ROWS*DD];
__device__ float g_v   [ROWS*DD];
__device__ float g_attn[ROWS*DD];
__device__ float g_x1  [ROWS*DD];
__device__ float g_x2  [ROWS*DD];
__device__ float g_kc  [CROWS*DD];
__device__ float g_vc  [CROWS*DD];
__device__ float g_proj[ROWS*2*FFF];
__device__ float g_ffmid[ROWS*FFF];

// ---------------- LayerNorm: one block per row of 640 ----------------
__global__ void ln_kernel(const float* __restrict__ x,
                          const float* __restrict__ w,
                          const float* __restrict__ b,
                          float* __restrict__ out) {
    __shared__ float red[2][8];
    int row = blockIdx.x;
    int tid = threadIdx.x;          // 160 threads, each float4
    const float* xr = x + (size_t)row * DD;
    float4 v = *(const float4*)&xr[tid * 4];
    float s  = v.x + v.y + v.z + v.w;
    float sq = v.x*v.x + v.y*v.y + v.z*v.z + v.w*v.w;
    // warp reduce
    for (int o = 16; o > 0; o >>= 1) {
        s  += __shfl_down_sync(0xffffffffu, s,  o);
        sq += __shfl_down_sync(0xffffffffu, sq, o);
    }
    int wid = tid >> 5, lane = tid & 31;
    if (lane == 0) { red[0][wid] = s; red[1][wid] = sq; }
    __syncthreads();
    if (tid == 0) {
        float S = 0.f, Q = 0.f;
        for (int i = 0; i < 5; i++) { S += red[0][i]; Q += red[1][i]; }
        float mean = S / (float)DD;
        float var  = Q / (float)DD - mean * mean;
        red[0][0] = mean;
        red[1][0] = rsqrtf(var + 1e-5f);
    }
    __syncthreads();
    float mean = red[0][0], inv = red[1][0];
    float4 wv = *(const float4*)&w[tid * 4];
    float4 bv = *(const float4*)&b[tid * 4];
    float4 o4;
    o4.x = (v.x - mean) * inv * wv.x + bv.x;
    o4.y = (v.y - mean) * inv * wv.y + bv.y;
    o4.z = (v.z - mean) * inv * wv.z + bv.z;
    o4.w = (v.w - mean) * inv * wv.w + bv.w;
    *(float4*)&out[(size_t)row * DD + tid * 4] = o4;
}

// ---------------- SGEMM: C[M,N] = A[M,K] @ B[K,N] (+bias)(+res) ----------------
// 128x128 tile, BK=8, 256 threads, 8x8 per thread (2x2 quads of 4x4).
template<int ADD_BIAS, int ADD_RES>
__global__ __launch_bounds__(256)
void sgemm_kernel(const float* __restrict__ A, const float* __restrict__ Bm,
                  const float* __restrict__ bias, const float* __restrict__ res,
                  float* __restrict__ C, int M, int N, int K) {
    __shared__ float As[8][132];   // transposed A tile, 132 stride (528B = 33*16, float4-aligned rows)
    __shared__ float Bs[8][128];
    int tid = threadIdx.x;
    int tx = tid & 15, ty = tid >> 4;
    int mbase = blockIdx.y * 128, nbase = blockIdx.x * 128;

    int arow = tid >> 1;            // 0..127
    int ak0  = (tid & 1) * 4;       // 0 or 4
    int brow = tid >> 5;            // 0..7
    int bcol = (tid & 31) * 4;      // 0..124

    float acc[2][2][4][4];
    #pragma unroll
    for (int a = 0; a < 2; a++)
      #pragma unroll
      for (int b = 0; b < 2; b++)
        #pragma unroll
        for (int i = 0; i < 4; i++)
          #pragma unroll
          for (int j = 0; j < 4; j++) acc[a][b][i][j] = 0.f;

    for (int kt = 0; kt < K; kt += 8) {
        // load A tile (guard M), store transposed
        float4 av = make_float4(0.f, 0.f, 0.f, 0.f);
        int gr = mbase + arow;
        if (gr < M) av = *(const float4*)&A[(size_t)gr * K + kt + ak0];
        As[ak0 + 0][arow] = av.x;
        As[ak0 + 1][arow] = av.y;
        As[ak0 + 2][arow] = av.z;
        As[ak0 + 3][arow] = av.w;
        // load B tile (N, K always in range here)
        float4 bv = *(const float4*)&Bm[(size_t)(kt + brow) * N + nbase + bcol];
        *(float4*)&Bs[brow][bcol] = bv;
        __syncthreads();

        #pragma unroll
        for (int k = 0; k < 8; k++) {
            float4 a0 = *(const float4*)&As[k][ty * 4];
            float4 a1 = *(const float4*)&As[k][64 + ty * 4];
            float4 b0 = *(const float4*)&Bs[k][tx * 4];
            float4 b1 = *(const float4*)&Bs[k][64 + tx * 4];
            float ar[2][4] = {{a0.x, a0.y, a0.z, a0.w}, {a1.x, a1.y, a1.z, a1.w}};
            float br[2][4] = {{b0.x, b0.y, b0.z, b0.w}, {b1.x, b1.y, b1.z, b1.w}};
            #pragma unroll
            for (int qi = 0; qi < 2; qi++)
              #pragma unroll
              for (int i = 0; i < 4; i++)
                #pragma unroll
                for (int qj = 0; qj < 2; qj++)
                  #pragma unroll
                  for (int j = 0; j < 4; j++)
                    acc[qi][qj][i][j] += ar[qi][i] * br[qj][j];
        }
        __syncthreads();
    }

    #pragma unroll
    for (int qi = 0; qi < 2; qi++) {
        #pragma unroll
        for (int i = 0; i < 4; i++) {
            int r = mbase + qi * 64 + ty * 4 + i;
            if (r >= M) continue;
            #pragma unroll
            for (int qj = 0; qj < 2; qj++) {
                int c = nbase + qj * 64 + tx * 4;
                float4 val = make_float4(acc[qi][qj][i][0], acc[qi][qj][i][1],
                                         acc[qi][qj][i][2], acc[qi][qj][i][3]);
                if (ADD_BIAS) {
                    float4 bv = *(const float4*)&bias[c];
                    val.x += bv.x; val.y += bv.y; val.z += bv.z; val.w += bv.w;
                }
                if (ADD_RES) {
                    float4 rv = *(const float4*)&res[(size_t)r * N + c];
                    val.x += rv.x; val.y += rv.y; val.z += rv.z; val.w += rv.w;
                }
                *(float4*)&C[(size_t)r * N + c] = val;
            }
        }
    }
}

// ---------------- Flash self-attention (fp32) ----------------
// One block: 64 query rows for one (b,h). Loops over 4096 keys in chunks of 64.
// smem: Qt[80][68], Kt[80][68] (transposed, pad 68 keeps float4 alignment),
//       Vs[64][80], Ss[64][64].
#define FA_SMEM ((80*68 + 80*68 + 64*80 + 64*64) * 4)
__global__ __launch_bounds__(256)
void self_attn_kernel(const float* __restrict__ q, const float* __restrict__ k,
                      const float* __restrict__ v, float* __restrict__ out) {
    extern __shared__ float sm[];
    float* Qt = sm;                 // [80][68]
    float* Kt = Qt + 80 * 68;       // [80][68]
    float* Vs = Kt + 80 * 68;       // [64][80]
    float* Ss = Vs + 64 * 80;       // [64][64]

    int bh = blockIdx.y;
    int b = bh >> 3, h = bh & 7;
    int qbase = blockIdx.x * 64;
    const float* qp = q + (size_t)b * NN * DD + h * DHD;
    const float* kp = k + (size_t)b * NN * DD + h * DHD;
    const float* vp = v + (size_t)b * NN * DD + h * DHD;

    int tid = threadIdx.x;
    int tx = tid & 15, ty = tid >> 4;   // S-phase 16x16 map
    int rr = tid >> 2, cc = tid & 3;    // softmax/O-phase 64x4 map

    // Load Q tile transposed
    for (int i = tid; i < 64 * 80; i += 256) {
        int r = i / 80, d = i % 80;
        Qt[d * 68 + r] = qp[(size_t)(qbase + r) * DD + d];
    }

    float m = -1e30f, l = 0.f;
    float oacc[20];
    #pragma unroll
    for (int i = 0; i < 20; i++) oacc[i] = 0.f;
    const float scale = 0.11180339887498949f;   // 80^-0.5

    for (int kb = 0; kb < NN; kb += 64) {
        __syncthreads();   // protect Kt/Vs/Ss from previous iteration readers
        for (int i = tid; i < 64 * 80; i += 256) {
            int r = i / 80, d = i % 80;
            float kval = kp[(size_t)(kb + r) * DD + d];
            float vval = vp[(size_t)(kb + r) * DD + d];
            Kt[d * 68 + r] = kval;
            Vs[r * 80 + d] = vval;
        }
        __syncthreads();

        // ---- S = scale * Q K^T  (16x16 threads, 4x4 each) ----
        float acc[4][4];
        #pragma unroll
        for (int i = 0; i < 4; i++)
          #pragma unroll
          for (int j = 0; j < 4; j++) acc[i][j] = 0.f;
        #pragma unroll 4
        for (int d = 0; d < 80; d++) {
            float4 aq = *(const float4*)&Qt[d * 68 + ty * 4];
            float4 ak = *(const float4*)&Kt[d * 68 + tx * 4];
            float a[4] = {aq.x, aq.y, aq.z, aq.w};
            float kk[4] = {ak.x, ak.y, ak.z, ak.w};
            #pragma unroll
            for (int i = 0; i < 4; i++)
              #pragma unroll
              for (int j = 0; j < 4; j++) acc[i][j] += a[i] * kk[j];
        }
        #pragma unroll
        for (int i = 0; i < 4; i++)
          #pragma unroll
          for (int j = 0; j < 4; j++)
            Ss[(ty * 4 + i) * 64 + tx * 4 + j] = acc[i][j] * scale;
        __syncthreads();

        // ---- online softmax + O accumulation (4 threads per row) ----
        float sv[16];
        float mx = m;
        #pragma unroll
        for (int j = 0; j < 16; j++) {
            sv[j] = Ss[rr * 64 + cc * 16 + j];
            mx = fmaxf(mx, sv[j]);
        }
        mx = fmaxf(mx, __shfl_xor_sync(0xffffffffu, mx, 1));
        mx = fmaxf(mx, __shfl_xor_sync(0xffffffffu, mx, 2));
        float alpha = expf(m - mx);
        float sum = 0.f;
        #pragma unroll
        for (int j = 0; j < 16; j++) {
            float p = expf(sv[j] - mx);
            Ss[rr * 64 + cc * 16 + j] = p;
            sum += p;
        }
        sum += __shfl_xor_sync(0xffffffffu, sum, 1);
        sum += __shfl_xor_sync(0xffffffffu, sum, 2);
        m = mx;
        l = l * alpha + sum;
        #pragma unroll
        for (int i = 0; i < 20; i++) oacc[i] *= alpha;
        __syncwarp();   // P row written by this 4-lane group (same warp)
        for (int j = 0; j < 64; j++) {
            float p = Ss[rr * 64 + j];
            const float* vrow = &Vs[j * 80 + cc * 20];
            #pragma unroll
            for (int i4 = 0; i4 < 5; i4++) {
                float4 vv = *(const float4*)&vrow[i4 * 4];
                oacc[i4 * 4 + 0] += p * vv.x;
                oacc[i4 * 4 + 1] += p * vv.y;
                oacc[i4 * 4 + 2] += p * vv.z;
                oacc[i4 * 4 + 3] += p * vv.w;
            }
        }
    }

    float inv = 1.0f / l;
    float* op = out + (size_t)b * NN * DD + h * DHD
                    + (size_t)(qbase + rr) * DD + cc * 20;
    #pragma unroll
    for (int i4 = 0; i4 < 5; i4++) {
        float4 o4 = make_float4(oacc[i4*4+0] * inv, oacc[i4*4+1] * inv,
                                oacc[i4*4+2] * inv, oacc[i4*4+3] * inv);
        *(float4*)&op[i4 * 4] = o4;
    }
}

// ---------------- Cross attention (77 keys, fits in smem) ----------------
#define CA_SMEM ((64*80 + 77*80 + 77*80 + 64*80 + 64) * 4)
__global__ __launch_bounds__(256)
void cross_attn_kernel(const float* __restrict__ q, const float* __restrict__ kc,
                       const float* __restrict__ vc, float* __restrict__ out) {
    extern __shared__ float sm[];
    float* Qs = sm;                  // [64][80]
    float* Ks = Qs + 64 * 80;        // [77][80]
    float* Vs = Ks + 77 * 80;        // [77][80]
    float* Ss = Vs + 77 * 80;        // [64][80] (77 used)
    float* lrow = Ss + 64 * 80;      // [64]

    int bh = blockIdx.y;
    int b = bh >> 3, h = bh & 7;
    int qbase = blockIdx.x * 64;
    const float* qp = q  + (size_t)b * NN * DD  + h * DHD;
    const float* kp = kc + (size_t)b * CNN * DD + h * DHD;
    const float* vp = vc + (size_t)b * CNN * DD + h * DHD;

    int tid = threadIdx.x;
    for (int i = tid; i < 64 * 80; i += 256) {
        int r = i / 80, d = i % 80;
        Qs[i] = qp[(size_t)(qbase + r) * DD + d];
    }
    for (int i = tid; i < 77 * 80; i += 256) {
        int r = i / 80, d = i % 80;
        Ks[i] = kp[(size_t)r * DD + d];
        Vs[i] = vp[(size_t)r * DD + d];
    }
    __syncthreads();

    int rr = tid >> 2, cc = tid & 3;
    const float scale = 0.11180339887498949f;

    // phase 1: scores + softmax (strided over j by 4 lanes)
    float mx = -1e30f;
    for (int j = cc; j < CNN; j += 4) {
        const float* qrow = &Qs[rr * 80];
        const float* krow = &Ks[j * 80];
        float s = 0.f;
        #pragma unroll
        for (int d4 = 0; d4 < 20; d4++) {
            float4 a  = *(const float4*)&qrow[d4 * 4];
            float4 kk = *(const float4*)&krow[d4 * 4];
            s += a.x*kk.x + a.y*kk.y + a.z*kk.z + a.w*kk.w;
        }
        s *= scale;
        Ss[rr * 80 + j] = s;
        mx = fmaxf(mx, s);
    }
    mx = fmaxf(mx, __shfl_xor_sync(0xffffffffu, mx, 1));
    mx = fmaxf(mx, __shfl_xor_sync(0xffffffffu, mx, 2));
    float sum = 0.f;
    for (int j = cc; j < CNN; j += 4) {
        float p = expf(Ss[rr * 80 + j] - mx);
        Ss[rr * 80 + j] = p;
        sum += p;
    }
    sum += __shfl_xor_sync(0xffffffffu, sum, 1);
    sum += __shfl_xor_sync(0xffffffffu, sum, 2);
    if (cc == 0) lrow[rr] = sum;
    __syncwarp();

    // phase 2: O = P V / l  (4 lanes split the 80 dims, 20 each)
    float o[20];
    #pragma unroll
    for (int i = 0; i < 20; i++) o[i] = 0.f;
    for (int j = 0; j < CNN; j++) {
        float p = Ss[rr * 80 + j];
        const float* vrow = &Vs[j * 80 + cc * 20];
        #pragma unroll
        for (int i4 = 0; i4 < 5; i4++) {
            float4 vv = *(const float4*)&vrow[i4 * 4];
            o[i4*4+0] += p * vv.x;
            o[i4*4+1] += p * vv.y;
            o[i4*4+2] += p * vv.z;
            o[i4*4+3] += p * vv.w;
        }
    }
    float inv = 1.0f / lrow[rr];
    float* op = out + (size_t)b * NN * DD + h * DHD
                    + (size_t)(qbase + rr) * DD + cc * 20;
    #pragma unroll
    for (int i4 = 0; i4 < 5; i4++) {
        float4 o4 = make_float4(o[i4*4+0]*inv, o[i4*4+1]*inv, o[i4*4+2]*inv, o[i4*4+3]*inv);
        *(float4*)&op[i4 * 4] = o4;
    }
}

// ---------------- GEGLU: out = a * gelu_exact(g) ----------------
__global__ void geglu_kernel(const float* __restrict__ proj, float* __restrict__ out) {
    int idx = blockIdx.x * blockDim.x + threadIdx.x;
    int p = idx * 4;                       // linear position in [ROWS x FFF]
    int r = p / FFF;
    int j = p - r * FFF;
    float4 a = *(const float4*)&proj[(size_t)r * (2 * FFF) + j];
    float4 g = *(const float4*)&proj[(size_t)r * (2 * FFF) + FFF + j];
    const float c = 0.70710678118654752f;
    float4 o4;
    o4.x = a.x * 0.5f * g.x * (1.f + erff(g.x * c));
    o4.y = a.y * 0.5f * g.y * (1.f + erff(g.y * c));
    o4.z = a.z * 0.5f * g.z * (1.f + erff(g.z * c));
    o4.w = a.w * 0.5f * g.w * (1.f + erff(g.w * c));
    *(float4*)&out[(size_t)r * FFF + j] = o4;
}

// ---------------- launch ----------------
extern "C" void kernel_launch(void* const* d_in, const int* in_sizes, int n_in,
                              void* d_out, int out_size) {
    const float* x       = (const float*)d_in[0];
    const float* context = (const float*)d_in[1];
    const float* ln1_w = (const float*)d_in[2];
    const float* ln1_b = (const float*)d_in[3];
    const float* ln2_w = (const float*)d_in[4];
    const float* ln2_b = (const float*)d_in[5];
    const float* ln3_w = (const float*)d_in[6];
    const float* ln3_b = (const float*)d_in[7];
    const float* wq1 = (const float*)d_in[8];
    const float* wk1 = (const float*)d_in[9];
    const float* wv1 = (const float*)d_in[10];
    const float* wo1 = (const float*)d_in[11];
    const float* bo1 = (const float*)d_in[12];
    const float* wq2 = (const float*)d_in[13];
    const float* wk2 = (const float*)d_in[14];
    const float* wv2 = (const float*)d_in[15];
    const float* wo2 = (const float*)d_in[16];
    const float* bo2 = (const float*)d_in[17];
    const float* w_ff1 = (const float*)d_in[18];
    const float* b_ff1 = (const float*)d_in[19];
    const float* w_ff2 = (const float*)d_in[20];
    const float* b_ff2 = (const float*)d_in[21];
    float* out = (float*)d_out;

    float *h, *q, *k, *v, *attn, *x1, *x2, *kc, *vc, *proj, *ffmid;
    cudaGetSymbolAddress((void**)&h, g_h);
    cudaGetSymbolAddress((void**)&q, g_q);
    cudaGetSymbolAddress((void**)&k, g_k);
    cudaGetSymbolAddress((void**)&v, g_v);
    cudaGetSymbolAddress((void**)&attn, g_attn);
    cudaGetSymbolAddress((void**)&x1, g_x1);
    cudaGetSymbolAddress((void**)&x2, g_x2);
    cudaGetSymbolAddress((void**)&kc, g_kc);
    cudaGetSymbolAddress((void**)&vc, g_vc);
    cudaGetSymbolAddress((void**)&proj, g_proj);
    cudaGetSymbolAddress((void**)&ffmid, g_ffmid);

    cudaFuncSetAttribute(self_attn_kernel,  cudaFuncAttributeMaxDynamicSharedMemorySize, FA_SMEM);
    cudaFuncSetAttribute(cross_attn_kernel, cudaFuncAttributeMaxDynamicSharedMemorySize, CA_SMEM);

    dim3 g640(DD / 128, ROWS / 128);          // (5, 64)
    dim3 gff1(2 * FFF / 128, ROWS / 128);     // (40, 64)
    dim3 gctx(DD / 128, (CROWS + 127) / 128); // (5, 2)
    dim3 gattn(NN / 64, BB * HH);             // (64, 16)

    // ----- self-attention block -----
    ln_kernel<<<ROWS, 160>>>(x, ln1_w, ln1_b, h);
    sgemm_kernel<0,0><<<g640, 256>>>(h, wq1, nullptr, nullptr, q, ROWS, DD, DD);
    sgemm_kernel<0,0><<<g640, 256>>>(h, wk1, nullptr, nullptr, k, ROWS, DD, DD);
    sgemm_kernel<0,0><<<g640, 256>>>(h, wv1, nullptr, nullptr, v, ROWS, DD, DD);
    self_attn_kernel<<<gattn, 256, FA_SMEM>>>(q, k, v, attn);
    sgemm_kernel<1,1><<<g640, 256>>>(attn, wo1, bo1, x, x1, ROWS, DD, DD);

    // ----- cross-attention block -----
    ln_kernel<<<ROWS, 160>>>(x1, ln2_w, ln2_b, h);
    sgemm_kernel<0,0><<<g640, 256>>>(h, wq2, nullptr, nullptr, q, ROWS, DD, DD);
    sgemm_kernel<0,0><<<gctx, 256>>>(context, wk2, nullptr, nullptr, kc, CROWS, DD, CDD);
    sgemm_kernel<0,0><<<gctx, 256>>>(context, wv2, nullptr, nullptr, vc, CROWS, DD, CDD);
    cross_attn_kernel<<<gattn, 256, CA_SMEM>>>(q, kc, vc, attn);
    sgemm_kernel<1,1><<<g640, 256>>>(attn, wo2, bo2, x1, x2, ROWS, DD, DD);

    // ----- GEGLU FF block -----
    ln_kernel<<<ROWS, 160>>>(x2, ln3_w, ln3_b, h);
    sgemm_kernel<1,0><<<gff1, 256>>>(h, w_ff1, b_ff1, nullptr, proj, ROWS, 2 * FFF, DD);
    geglu_kernel<<<(ROWS * FFF) / (256 * 4), 256>>>(proj, ffmid);
    sgemm_kernel<1,1><<<g640, 256>>>(ffmid, w_ff2, b_ff2, x2, out, ROWS, DD, FFF);
}

// round 4
// speedup vs baseline: 5.6012x; 5.6012x over previous
#include <cuda_runtime.h>
#include <cuda_bf16.h>
#include <math.h>
#include <cstdint>

// Problem dims
#define BB   2
#define NN   4096
#define DD   640
#define HH   8
#define DHD  80
#define CNN  77
#define CDD  768
#define FFF  2560
#define ROWS (BB*NN)          // 8192
#define CROWS (BB*CNN)        // 154

// ================= mma.sync / ldmatrix helpers (sm_80+, compiles for sm_100) ==
__device__ __forceinline__ void ldsm4(uint32_t* r, uint32_t addr) {
    asm volatile("ldmatrix.sync.aligned.m8n8.x4.shared.b16 {%0,%1,%2,%3}, [%4];"
        : "=r"(r[0]), "=r"(r[1]), "=r"(r[2]), "=r"(r[3]) : "r"(addr));
}
__device__ __forceinline__ void ldsm4t(uint32_t* r, uint32_t addr) {
    asm volatile("ldmatrix.sync.aligned.m8n8.x4.trans.shared.b16 {%0,%1,%2,%3}, [%4];"
        : "=r"(r[0]), "=r"(r[1]), "=r"(r[2]), "=r"(r[3]) : "r"(addr));
}
__device__ __forceinline__ void mma16816(float* c, const uint32_t* a, uint32_t b0, uint32_t b1) {
    asm volatile("mma.sync.aligned.m16n8k16.row.col.f32.bf16.bf16.f32 "
        "{%0,%1,%2,%3}, {%4,%5,%6,%7}, {%8,%9}, {%0,%1,%2,%3};"
        : "+f"(c[0]), "+f"(c[1]), "+f"(c[2]), "+f"(c[3])
        : "r"(a[0]), "r"(a[1]), "r"(a[2]), "r"(a[3]), "r"(b0), "r"(b1));
}
__device__ __forceinline__ uint32_t smaddr(const void* p) {
    return (uint32_t)__cvta_generic_to_shared(p);
}
__device__ __forceinline__ uint32_t packbf2(float lo, float hi) {
    __nv_bfloat162 t = __floats2bfloat162_rn(lo, hi);
    return *(uint32_t*)&t;
}

// ================= scratch (device globals) =================
__device__ float g_x1  [ROWS*DD];
__device__ float g_x2  [ROWS*DD];
__device__ float g_proj[ROWS*2*FFF];

__device__ __nv_bfloat16 g_hbf   [ROWS*DD];
__device__ __nv_bfloat16 g_qbf   [ROWS*DD];
__device__ __nv_bfloat16 g_kbf   [ROWS*DD];
__device__ __nv_bfloat16 g_vbf   [ROWS*DD];
__device__ __nv_bfloat16 g_attnbf[ROWS*DD];
__device__ __nv_bfloat16 g_ffbf  [ROWS*FFF];
__device__ __nv_bfloat16 g_ctxbf [CROWS*CDD];
__device__ __nv_bfloat16 g_kcbf  [CROWS*DD];
__device__ __nv_bfloat16 g_vcbf  [CROWS*DD];
__device__ __nv_bfloat16 g_wq1t[DD*DD], g_wk1t[DD*DD], g_wv1t[DD*DD], g_wo1t[DD*DD];
__device__ __nv_bfloat16 g_wq2t[DD*DD], g_wo2t[DD*DD];
__device__ __nv_bfloat16 g_wk2t[DD*CDD], g_wv2t[DD*CDD];
__device__ __nv_bfloat16 g_wff1t[2*FFF*DD];
__device__ __nv_bfloat16 g_wff2t[DD*FFF];

// ================= weight transpose f32 -> bf16 : W[K,N] -> Wt[N,K] ==========
__global__ void wtrans_kernel(const float* __restrict__ W, __nv_bfloat16* __restrict__ Wt,
                              int K, int N) {
    __shared__ float tsm[32][33];
    int k0 = blockIdx.y * 32, n0 = blockIdx.x * 32;
    tsm[threadIdx.y][threadIdx.x] = W[(size_t)(k0 + threadIdx.y) * N + n0 + threadIdx.x];
    __syncthreads();
    Wt[(size_t)(n0 + threadIdx.y) * K + k0 + threadIdx.x] = __float2bfloat16(tsm[threadIdx.x][threadIdx.y]);
}

__global__ void f2b_kernel(const float* __restrict__ in, __nv_bfloat16* __restrict__ out, int n4) {
    int i = blockIdx.x * blockDim.x + threadIdx.x;
    if (i >= n4) return;
    float4 v = ((const float4*)in)[i];
    uint2 pk;
    pk.x = packbf2(v.x, v.y);
    pk.y = packbf2(v.z, v.w);
    ((uint2*)out)[i] = pk;
}

// ================= HMMA bf16 GEMM =================
// C[M,N] = A[M,K] @ Bt[N,K]^T (+bias)(+res). A,Bt bf16 row-major; C fp32 or bf16.
// 128x128 tile, BK=32, 8 warps (2M x 4N), warp tile 64x32, m16n8k16 frags.
template<int ADD_BIAS, int ADD_RES, int OUT_BF16>
__global__ __launch_bounds__(256)
void hmma_gemm(const __nv_bfloat16* __restrict__ A, const __nv_bfloat16* __restrict__ Bt,
               const float* __restrict__ bias, const float* __restrict__ res,
               void* __restrict__ Cv, int M, int N, int K) {
    __shared__ __nv_bfloat16 As[128][40];   // 80B row stride -> conflict-free ldmatrix
    __shared__ __nv_bfloat16 Bs[128][40];
    int tid = threadIdx.x;
    int wid = tid >> 5, lane = tid & 31;
    int wm = wid & 1, wn = wid >> 1;
    int mbase = blockIdx.y * 128, nbase = blockIdx.x * 128;

    float acc[4][4][4];
    #pragma unroll
    for (int a = 0; a < 4; a++)
      #pragma unroll
      for (int b = 0; b < 4; b++)
        #pragma unroll
        for (int c = 0; c < 4; c++) acc[a][b][c] = 0.f;

    // global->smem mapping: 512 uint4 chunks per operand tile; 2 per thread
    int r0 = tid >> 1, c0 = tid & 1;                 // row 0..127, 16B-chunk 0..1 (first half)
    // second chunk: idx+256 -> same layout shifted
    for (int kt = 0; kt < K; kt += 32) {
        const uint4 z = make_uint4(0u, 0u, 0u, 0u);
        // each thread: 2 chunks of A, 2 of B. idx = tid, tid+256; row=idx>>2, c4=idx&3
        int i0 = tid, i1 = tid + 256;
        int ar0 = i0 >> 2, ac0 = i0 & 3, ar1 = i1 >> 2, ac1 = i1 & 3;
        uint4 av0 = (mbase + ar0 < M) ? *(const uint4*)(A + (size_t)(mbase + ar0) * K + kt + ac0 * 8) : z;
        uint4 av1 = (mbase + ar1 < M) ? *(const uint4*)(A + (size_t)(mbase + ar1) * K + kt + ac1 * 8) : z;
        uint4 bv0 = *(const uint4*)(Bt + (size_t)(nbase + ar0) * K + kt + ac0 * 8);
        uint4 bv1 = *(const uint4*)(Bt + (size_t)(nbase + ar1) * K + kt + ac1 * 8);
        __syncthreads();   // previous iteration's consumers done
        *(uint4*)&As[ar0][ac0 * 8] = av0;
        *(uint4*)&As[ar1][ac1 * 8] = av1;
        *(uint4*)&Bs[ar0][ac0 * 8] = bv0;
        *(uint4*)&Bs[ar1][ac1 * 8] = bv1;
        __syncthreads();

        #pragma unroll
        for (int ks = 0; ks < 2; ks++) {
            int k16 = ks * 16;
            uint32_t af[4][4];
            #pragma unroll
            for (int mt = 0; mt < 4; mt++)
                ldsm4(af[mt], smaddr(&As[wm * 64 + mt * 16 + (lane & 15)][k16 + 8 * (lane >> 4)]));
            uint32_t bf[2][4];
            int mi = lane >> 3, wr = lane & 7;
            #pragma unroll
            for (int p = 0; p < 2; p++)
                ldsm4(bf[p], smaddr(&Bs[wn * 32 + p * 16 + (mi >> 1) * 8 + wr][k16 + (mi & 1) * 8]));
            #pragma unroll
            for (int mt = 0; mt < 4; mt++)
              #pragma unroll
              for (int nt = 0; nt < 4; nt++)
                mma16816(acc[mt][nt], af[mt], bf[nt >> 1][(nt & 1) * 2], bf[nt >> 1][(nt & 1) * 2 + 1]);
        }
    }
    (void)r0; (void)c0;

    // epilogue: C frag m16n8: lane -> rows lane/4, lane/4+8; cols 2*(lane%4)+{0,1}
    #pragma unroll
    for (int mt = 0; mt < 4; mt++) {
        int rb = mbase + wm * 64 + mt * 16 + (lane >> 2);
        #pragma unroll
        for (int half = 0; half < 2; half++) {
            int r = rb + half * 8;
            if (r >= M) continue;
            #pragma unroll
            for (int nt = 0; nt < 4; nt++) {
                int c = nbase + wn * 32 + nt * 8 + (lane & 3) * 2;
                float v0 = acc[mt][nt][half * 2 + 0];
                float v1 = acc[mt][nt][half * 2 + 1];
                if (ADD_BIAS) { v0 += bias[c]; v1 += bias[c + 1]; }
                if (ADD_RES) {
                    float2 rv = *(const float2*)&res[(size_t)r * N + c];
                    v0 += rv.x; v1 += rv.y;
                }
                if (OUT_BF16) {
                    *(uint32_t*)((__nv_bfloat16*)Cv + (size_t)r * N + c) = packbf2(v0, v1);
                } else {
                    *(float2*)((float*)Cv + (size_t)r * N + c) = make_float2(v0, v1);
                }
            }
        }
    }
}

// ================= LayerNorm (fp32 in, bf16 out) =================
__global__ void ln_kernel(const float* __restrict__ x,
                          const float* __restrict__ w,
                          const float* __restrict__ b,
                          __nv_bfloat16* __restrict__ out) {
    __shared__ float red[2][8];
    int row = blockIdx.x;
    int tid = threadIdx.x;          // 160 threads
    const float* xr = x + (size_t)row * DD;
    float4 v = *(const float4*)&xr[tid * 4];
    float s  = v.x + v.y + v.z + v.w;
    float sq = v.x*v.x + v.y*v.y + v.z*v.z + v.w*v.w;
    for (int o = 16; o > 0; o >>= 1) {
        s  += __shfl_down_sync(0xffffffffu, s,  o);
        sq += __shfl_down_sync(0xffffffffu, sq, o);
    }
    int wid = tid >> 5, lane = tid & 31;
    if (lane == 0) { red[0][wid] = s; red[1][wid] = sq; }
    __syncthreads();
    if (tid == 0) {
        float S = 0.f, Q = 0.f;
        for (int i = 0; i < 5; i++) { S += red[0][i]; Q += red[1][i]; }
        float mean = S / (float)DD;
        float var  = Q / (float)DD - mean * mean;
        red[0][0] = mean;
        red[1][0] = rsqrtf(var + 1e-5f);
    }
    __syncthreads();
    float mean = red[0][0], inv = red[1][0];
    float4 wv = *(const float4*)&w[tid * 4];
    float4 bv = *(const float4*)&b[tid * 4];
    float o0 = (v.x - mean) * inv * wv.x + bv.x;
    float o1 = (v.y - mean) * inv * wv.y + bv.y;
    float o2 = (v.z - mean) * inv * wv.z + bv.z;
    float o3 = (v.w - mean) * inv * wv.w + bv.w;
    uint2 pk;
    pk.x = packbf2(o0, o1);
    pk.y = packbf2(o2, o3);
    *(uint2*)&out[(size_t)row * DD + tid * 4] = pk;
}

// ================= HMMA flash self-attention (bf16 in/out, fp32 softmax) =====
// Block: 64 queries x one (b,h); 4 warps, each warp owns m16 query rows.
// Loops 4096 keys in 64-chunks. QK^T and PV on tensor cores; P stays in regs.
#define ATT_PAD 88   // 176B row stride -> conflict-free ldmatrix
__global__ __launch_bounds__(128)
void self_attn_hmma(const __nv_bfloat16* __restrict__ q, const __nv_bfloat16* __restrict__ k,
                    const __nv_bfloat16* __restrict__ v, __nv_bfloat16* __restrict__ out) {
    __shared__ __nv_bfloat16 Qs[64][ATT_PAD];
    __shared__ __nv_bfloat16 Ks[64][ATT_PAD];
    __shared__ __nv_bfloat16 Vs[64][ATT_PAD];

    int bh = blockIdx.y;
    int b = bh >> 3, h = bh & 7;
    int qbase = blockIdx.x * 64;
    const __nv_bfloat16* qp = q + (size_t)b * NN * DD + h * DHD;
    const __nv_bfloat16* kp = k + (size_t)b * NN * DD + h * DHD;
    const __nv_bfloat16* vp = v + (size_t)b * NN * DD + h * DHD;

    int tid = threadIdx.x, wid = tid >> 5, lane = tid & 31;
    int mi = lane >> 3, wr = lane & 7;

    for (int i = tid; i < 64 * 10; i += 128) {
        int r = i / 10, c = i % 10;
        *(uint4*)&Qs[r][c * 8] = *(const uint4*)(qp + (size_t)(qbase + r) * DD + c * 8);
    }

    float m0 = -1e30f, m1 = -1e30f, l0 = 0.f, l1 = 0.f;
    float oacc[10][4];
    #pragma unroll
    for (int t = 0; t < 10; t++)
      #pragma unroll
      for (int c = 0; c < 4; c++) oacc[t][c] = 0.f;
    const float scale = 0.11180339887498949f;   // 80^-0.5

    for (int kb = 0; kb < NN; kb += 64) {
        __syncthreads();
        for (int i = tid; i < 64 * 10; i += 128) {
            int r = i / 10, c = i % 10;
            *(uint4*)&Ks[r][c * 8] = *(const uint4*)(kp + (size_t)(kb + r) * DD + c * 8);
            *(uint4*)&Vs[r][c * 8] = *(const uint4*)(vp + (size_t)(kb + r) * DD + c * 8);
        }
        __syncthreads();

        // ---- S = Q K^T : warp computes m16 x 64 (8 n8 tiles) ----
        float s[8][4];
        #pragma unroll
        for (int t = 0; t < 8; t++)
          #pragma unroll
          for (int c = 0; c < 4; c++) s[t][c] = 0.f;
        #pragma unroll
        for (int ks = 0; ks < 5; ks++) {
            uint32_t af[4];
            ldsm4(af, smaddr(&Qs[wid * 16 + (lane & 15)][ks * 16 + 8 * (lane >> 4)]));
            #pragma unroll
            for (int p = 0; p < 4; p++) {
                uint32_t bf[4];
                ldsm4(bf, smaddr(&Ks[p * 16 + (mi >> 1) * 8 + wr][ks * 16 + (mi & 1) * 8]));
                mma16816(s[p * 2 + 0], af, bf[0], bf[1]);
                mma16816(s[p * 2 + 1], af, bf[2], bf[3]);
            }
        }

        // ---- online softmax (rows lane/4 and lane/4+8, 4 lanes per row) ----
        float rmax0 = -1e30f, rmax1 = -1e30f;
        #pragma unroll
        for (int t = 0; t < 8; t++) {
            s[t][0] *= scale; s[t][1] *= scale; s[t][2] *= scale; s[t][3] *= scale;
            rmax0 = fmaxf(rmax0, fmaxf(s[t][0], s[t][1]));
            rmax1 = fmaxf(rmax1, fmaxf(s[t][2], s[t][3]));
        }
        rmax0 = fmaxf(rmax0, __shfl_xor_sync(0xffffffffu, rmax0, 1));
        rmax0 = fmaxf(rmax0, __shfl_xor_sync(0xffffffffu, rmax0, 2));
        rmax1 = fmaxf(rmax1, __shfl_xor_sync(0xffffffffu, rmax1, 1));
        rmax1 = fmaxf(rmax1, __shfl_xor_sync(0xffffffffu, rmax1, 2));
        float nm0 = fmaxf(m0, rmax0), nm1 = fmaxf(m1, rmax1);
        float alpha0 = __expf(m0 - nm0), alpha1 = __expf(m1 - nm1);
        float sum0 = 0.f, sum1 = 0.f;
        #pragma unroll
        for (int t = 0; t < 8; t++) {
            s[t][0] = __expf(s[t][0] - nm0);
            s[t][1] = __expf(s[t][1] - nm0);
            s[t][2] = __expf(s[t][2] - nm1);
            s[t][3] = __expf(s[t][3] - nm1);
            sum0 += s[t][0] + s[t][1];
            sum1 += s[t][2] + s[t][3];
        }
        sum0 += __shfl_xor_sync(0xffffffffu, sum0, 1);
        sum0 += __shfl_xor_sync(0xffffffffu, sum0, 2);
        sum1 += __shfl_xor_sync(0xffffffffu, sum1, 1);
        sum1 += __shfl_xor_sync(0xffffffffu, sum1, 2);
        m0 = nm0; m1 = nm1;
        l0 = l0 * alpha0 + sum0;
        l1 = l1 * alpha1 + sum1;
        #pragma unroll
        for (int t = 0; t < 10; t++) {
            oacc[t][0] *= alpha0; oacc[t][1] *= alpha0;
            oacc[t][2] *= alpha1; oacc[t][3] *= alpha1;
        }

        // ---- P (C-frag fp32) -> A-frags bf16, pure register repack ----
        uint32_t pf[4][4];
        #pragma unroll
        for (int g = 0; g < 4; g++) {
            pf[g][0] = packbf2(s[2*g][0],   s[2*g][1]);
            pf[g][1] = packbf2(s[2*g][2],   s[2*g][3]);
            pf[g][2] = packbf2(s[2*g+1][0], s[2*g+1][1]);
            pf[g][3] = packbf2(s[2*g+1][2], s[2*g+1][3]);
        }
        // ---- O += P V  (V via ldmatrix.trans) ----
        #pragma unroll
        for (int g = 0; g < 4; g++) {
            #pragma unroll
            for (int p = 0; p < 5; p++) {
                uint32_t bf[4];
                ldsm4t(bf, smaddr(&Vs[g * 16 + (mi & 1) * 8 + wr][p * 16 + (mi >> 1) * 8]));
                mma16816(oacc[p * 2 + 0], pf[g], bf[0], bf[1]);
                mma16816(oacc[p * 2 + 1], pf[g], bf[2], bf[3]);
            }
        }
    }

    float inv0 = 1.f / l0, inv1 = 1.f / l1;
    int r0 = qbase + wid * 16 + (lane >> 2);
    __nv_bfloat16* op = out + (size_t)b * NN * DD + h * DHD;
    #pragma unroll
    for (int t = 0; t < 10; t++) {
        int d = t * 8 + (lane & 3) * 2;
        *(uint32_t*)(op + (size_t)r0 * DD + d)       = packbf2(oacc[t][0] * inv0, oacc[t][1] * inv0);
        *(uint32_t*)(op + (size_t)(r0 + 8) * DD + d) = packbf2(oacc[t][2] * inv1, oacc[t][3] * inv1);
    }
}

// ================= Cross attention (77 keys; bf16 I/O, fp32 inside) ==========
#define CA_SMEM ((64*80 + 77*80 + 77*80 + 64*80 + 64) * 4)
__global__ __launch_bounds__(256)
void cross_attn_kernel(const __nv_bfloat16* __restrict__ q, const __nv_bfloat16* __restrict__ kc,
                       const __nv_bfloat16* __restrict__ vc, __nv_bfloat16* __restrict__ out) {
    extern __shared__ float sm[];
    float* Qs = sm;
    float* Ks = Qs + 64 * 80;
    float* Vs = Ks + 77 * 80;
    float* Ss = Vs + 77 * 80;
    float* lrow = Ss + 64 * 80;

    int bh = blockIdx.y;
    int b = bh >> 3, h = bh & 7;
    int qbase = blockIdx.x * 64;
    const __nv_bfloat16* qp = q  + (size_t)b * NN * DD  + h * DHD;
    const __nv_bfloat16* kp = kc + (size_t)b * CNN * DD + h * DHD;
    const __nv_bfloat16* vp = vc + (size_t)b * CNN * DD + h * DHD;

    int tid = threadIdx.x;
    for (int i = tid; i < 64 * 80; i += 256) {
        int r = i / 80, d = i % 80;
        Qs[i] = __bfloat162float(qp[(size_t)(qbase + r) * DD + d]);
    }
    for (int i = tid; i < 77 * 80; i += 256) {
        int r = i / 80, d = i % 80;
        Ks[i] = __bfloat162float(kp[(size_t)r * DD + d]);
        Vs[i] = __bfloat162float(vp[(size_t)r * DD + d]);
    }
    __syncthreads();

    int rr = tid >> 2, cc = tid & 3;
    const float scale = 0.11180339887498949f;

    float mx = -1e30f;
    for (int j = cc; j < CNN; j += 4) {
        const float* qrow = &Qs[rr * 80];
        const float* krow = &Ks[j * 80];
        float s = 0.f;
        #pragma unroll
        for (int d4 = 0; d4 < 20; d4++) {
            float4 a  = *(const float4*)&qrow[d4 * 4];
            float4 kk = *(const float4*)&krow[d4 * 4];
            s += a.x*kk.x + a.y*kk.y + a.z*kk.z + a.w*kk.w;
        }
        s *= scale;
        Ss[rr * 80 + j] = s;
        mx = fmaxf(mx, s);
    }
    mx = fmaxf(mx, __shfl_xor_sync(0xffffffffu, mx, 1));
    mx = fmaxf(mx, __shfl_xor_sync(0xffffffffu, mx, 2));
    float sum = 0.f;
    for (int j = cc; j < CNN; j += 4) {
        float p = __expf(Ss[rr * 80 + j] - mx);
        Ss[rr * 80 + j] = p;
        sum += p;
    }
    sum += __shfl_xor_sync(0xffffffffu, sum, 1);
    sum += __shfl_xor_sync(0xffffffffu, sum, 2);
    if (cc == 0) lrow[rr] = sum;
    __syncwarp();

    float o[20];
    #pragma unroll
    for (int i = 0; i < 20; i++) o[i] = 0.f;
    for (int j = 0; j < CNN; j++) {
        float p = Ss[rr * 80 + j];
        const float* vrow = &Vs[j * 80 + cc * 20];
        #pragma unroll
        for (int i4 = 0; i4 < 5; i4++) {
            float4 vv = *(const float4*)&vrow[i4 * 4];
            o[i4*4+0] += p * vv.x;
            o[i4*4+1] += p * vv.y;
            o[i4*4+2] += p * vv.z;
            o[i4*4+3] += p * vv.w;
        }
    }
    float inv = 1.0f / lrow[rr];
    __nv_bfloat16* op = out + (size_t)b * NN * DD + h * DHD
                            + (size_t)(qbase + rr) * DD + cc * 20;
    #pragma unroll
    for (int i2 = 0; i2 < 10; i2++) {
        *(uint32_t*)(op + i2 * 2) = packbf2(o[i2*2+0] * inv, o[i2*2+1] * inv);
    }
}

// ================= GEGLU (fp32 in, bf16 out) =================
__global__ void geglu_kernel(const float* __restrict__ proj, __nv_bfloat16* __restrict__ out) {
    int idx = blockIdx.x * blockDim.x + threadIdx.x;
    int p = idx * 4;
    int r = p / FFF;
    int j = p - r * FFF;
    float4 a = *(const float4*)&proj[(size_t)r * (2 * FFF) + j];
    float4 g = *(const float4*)&proj[(size_t)r * (2 * FFF) + FFF + j];
    const float c = 0.70710678118654752f;
    float o0 = a.x * 0.5f * g.x * (1.f + erff(g.x * c));
    float o1 = a.y * 0.5f * g.y * (1.f + erff(g.y * c));
    float o2 = a.z * 0.5f * g.z * (1.f + erff(g.z * c));
    float o3 = a.w * 0.5f * g.w * (1.f + erff(g.w * c));
    uint2 pk;
    pk.x = packbf2(o0, o1);
    pk.y = packbf2(o2, o3);
    *(uint2*)&out[(size_t)r * FFF + j] = pk;
}

// ================= launch =================
extern "C" void kernel_launch(void* const* d_in, const int* in_sizes, int n_in,
                              void* d_out, int out_size) {
    const float* x       = (const float*)d_in[0];
    const float* context = (const float*)d_in[1];
    const float* ln1_w = (const float*)d_in[2];
    const float* ln1_b = (const float*)d_in[3];
    const float* ln2_w = (const float*)d_in[4];
    const float* ln2_b = (const float*)d_in[5];
    const float* ln3_w = (const float*)d_in[6];
    const float* ln3_b = (const float*)d_in[7];
    const float* wq1 = (const float*)d_in[8];
    const float* wk1 = (const float*)d_in[9];
    const float* wv1 = (const float*)d_in[10];
    const float* wo1 = (const float*)d_in[11];
    const float* bo1 = (const float*)d_in[12];
    const float* wq2 = (const float*)d_in[13];
    const float* wk2 = (const float*)d_in[14];
    const float* wv2 = (const float*)d_in[15];
    const float* wo2 = (const float*)d_in[16];
    const float* bo2 = (const float*)d_in[17];
    const float* b_ff1 = (const float*)d_in[19];
    const float* w_ff1 = (const float*)d_in[18];
    const float* w_ff2 = (const float*)d_in[20];
    const float* b_ff2 = (const float*)d_in[21];
    float* out = (float*)d_out;

    float *x1, *x2, *proj;
    __nv_bfloat16 *hbf, *qbf, *kbf, *vbf, *attnbf, *ffbf, *ctxbf, *kcbf, *vcbf;
    __nv_bfloat16 *wq1t, *wk1t, *wv1t, *wo1t, *wq2t, *wo2t, *wk2t, *wv2t, *wff1t, *wff2t;
    cudaGetSymbolAddress((void**)&x1, g_x1);
    cudaGetSymbolAddress((void**)&x2, g_x2);
    cudaGetSymbolAddress((void**)&proj, g_proj);
    cudaGetSymbolAddress((void**)&hbf, g_hbf);
    cudaGetSymbolAddress((void**)&qbf, g_qbf);
    cudaGetSymbolAddress((void**)&kbf, g_kbf);
    cudaGetSymbolAddress((void**)&vbf, g_vbf);
    cudaGetSymbolAddress((void**)&attnbf, g_attnbf);
    cudaGetSymbolAddress((void**)&ffbf, g_ffbf);
    cudaGetSymbolAddress((void**)&ctxbf, g_ctxbf);
    cudaGetSymbolAddress((void**)&kcbf, g_kcbf);
    cudaGetSymbolAddress((void**)&vcbf, g_vcbf);
    cudaGetSymbolAddress((void**)&wq1t, g_wq1t);
    cudaGetSymbolAddress((void**)&wk1t, g_wk1t);
    cudaGetSymbolAddress((void**)&wv1t, g_wv1t);
    cudaGetSymbolAddress((void**)&wo1t, g_wo1t);
    cudaGetSymbolAddress((void**)&wq2t, g_wq2t);
    cudaGetSymbolAddress((void**)&wo2t, g_wo2t);
    cudaGetSymbolAddress((void**)&wk2t, g_wk2t);
    cudaGetSymbolAddress((void**)&wv2t, g_wv2t);
    cudaGetSymbolAddress((void**)&wff1t, g_wff1t);
    cudaGetSymbolAddress((void**)&wff2t, g_wff2t);

    cudaFuncSetAttribute(cross_attn_kernel, cudaFuncAttributeMaxDynamicSharedMemorySize, CA_SMEM);

    dim3 tb(32, 32);
    wtrans_kernel<<<dim3(DD/32, DD/32), tb>>>(wq1, wq1t, DD, DD);
    wtrans_kernel<<<dim3(DD/32, DD/32), tb>>>(wk1, wk1t, DD, DD);
    wtrans_kernel<<<dim3(DD/32, DD/32), tb>>>(wv1, wv1t, DD, DD);
    wtrans_kernel<<<dim3(DD/32, DD/32), tb>>>(wo1, wo1t, DD, DD);
    wtrans_kernel<<<dim3(DD/32, DD/32), tb>>>(wq2, wq2t, DD, DD);
    wtrans_kernel<<<dim3(DD/32, CDD/32), tb>>>(wk2, wk2t, CDD, DD);
    wtrans_kernel<<<dim3(DD/32, CDD/32), tb>>>(wv2, wv2t, CDD, DD);
    wtrans_kernel<<<dim3(DD/32, DD/32), tb>>>(wo2, wo2t, DD, DD);
    wtrans_kernel<<<dim3(2*FFF/32, DD/32), tb>>>(w_ff1, wff1t, DD, 2*FFF);
    wtrans_kernel<<<dim3(DD/32, FFF/32), tb>>>(w_ff2, wff2t, FFF, DD);
    f2b_kernel<<<(CROWS*CDD/4 + 255)/256, 256>>>(context, ctxbf, CROWS*CDD/4);

    dim3 g640(DD/128, ROWS/128);            // (5, 64)
    dim3 gff1(2*FFF/128, ROWS/128);         // (40, 64)
    dim3 gctx(DD/128, (CROWS + 127)/128);   // (5, 2)
    dim3 gattn(NN/64, BB*HH);               // (64, 16)

    // ----- self-attention block -----
    ln_kernel<<<ROWS, 160>>>(x, ln1_w, ln1_b, hbf);
    hmma_gemm<0,0,1><<<g640, 256>>>(hbf, wq1t, nullptr, nullptr, qbf, ROWS, DD, DD);
    hmma_gemm<0,0,1><<<g640, 256>>>(hbf, wk1t, nullptr, nullptr, kbf, ROWS, DD, DD);
    hmma_gemm<0,0,1><<<g640, 256>>>(hbf, wv1t, nullptr, nullptr, vbf, ROWS, DD, DD);
    self_attn_hmma<<<gattn, 128>>>(qbf, kbf, vbf, attnbf);
    hmma_gemm<1,1,0><<<g640, 256>>>(attnbf, wo1t, bo1, x, x1, ROWS, DD, DD);

    // ----- cross-attention block -----
    ln_kernel<<<ROWS, 160>>>(x1, ln2_w, ln2_b, hbf);
    hmma_gemm<0,0,1><<<g640, 256>>>(hbf, wq2t, nullptr, nullptr, qbf, ROWS, DD, DD);
    hmma_gemm<0,0,1><<<gctx, 256>>>(ctxbf, wk2t, nullptr, nullptr, kcbf, CROWS, DD, CDD);
    hmma_gemm<0,0,1><<<gctx, 256>>>(ctxbf, wv2t, nullptr, nullptr, vcbf, CROWS, DD, CDD);
    cross_attn_kernel<<<gattn, 256, CA_SMEM>>>(qbf, kcbf, vcbf, attnbf);
    hmma_gemm<1,1,0><<<g640, 256>>>(attnbf, wo2t, bo2, x1, x2, ROWS, DD, DD);

    // ----- GEGLU FF block -----
    ln_kernel<<<ROWS, 160>>>(x2, ln3_w, ln3_b, hbf);
    hmma_gemm<1,0,0><<<gff1, 256>>>(hbf, wff1t, b_ff1, nullptr, proj, ROWS, 2*FFF, DD);
    geglu_kernel<<<(ROWS*FFF)/(256*4), 256>>>(proj, ffbf);
    hmma_gemm<1,1,0><<<g640, 256>>>(ffbf, wff2t, b_ff2, x2, out, ROWS, DD, FFF);
}

// round 5
// speedup vs baseline: 6.9640x; 1.2433x over previous
#include <cuda_runtime.h>
#include <cuda_bf16.h>
#include <math.h>
#include <cstdint>

// Problem dims
#define BB   2
#define NN   4096
#define DD   640
#define HH   8
#define DHD  80
#define CNN  77
#define CDD  768
#define FFF  2560
#define ROWS (BB*NN)          // 8192
#define CROWS (BB*CNN)        // 154
#define QKVS 1920             // fused qkv row stride
#define KVS  1280             // fused ctx k/v row stride

// ================= mma.sync / ldmatrix / cp.async helpers ====================
__device__ __forceinline__ void ldsm4(uint32_t* r, uint32_t addr) {
    asm volatile("ldmatrix.sync.aligned.m8n8.x4.shared.b16 {%0,%1,%2,%3}, [%4];"
        : "=r"(r[0]), "=r"(r[1]), "=r"(r[2]), "=r"(r[3]) : "r"(addr));
}
__device__ __forceinline__ void ldsm4t(uint32_t* r, uint32_t addr) {
    asm volatile("ldmatrix.sync.aligned.m8n8.x4.trans.shared.b16 {%0,%1,%2,%3}, [%4];"
        : "=r"(r[0]), "=r"(r[1]), "=r"(r[2]), "=r"(r[3]) : "r"(addr));
}
__device__ __forceinline__ void mma16816(float* c, const uint32_t* a, uint32_t b0, uint32_t b1) {
    asm volatile("mma.sync.aligned.m16n8k16.row.col.f32.bf16.bf16.f32 "
        "{%0,%1,%2,%3}, {%4,%5,%6,%7}, {%8,%9}, {%0,%1,%2,%3};"
        : "+f"(c[0]), "+f"(c[1]), "+f"(c[2]), "+f"(c[3])
        : "r"(a[0]), "r"(a[1]), "r"(a[2]), "r"(a[3]), "r"(b0), "r"(b1));
}
__device__ __forceinline__ uint32_t smaddr(const void* p) {
    return (uint32_t)__cvta_generic_to_shared(p);
}
__device__ __forceinline__ uint32_t packbf2(float lo, float hi) {
    __nv_bfloat162 t = __floats2bfloat162_rn(lo, hi);
    return *(uint32_t*)&t;
}
#define CPA16(dst, src) \
    asm volatile("cp.async.ca.shared.global [%0], [%1], 16;" :: "r"(dst), "l"(src))
#define CP_COMMIT() asm volatile("cp.async.commit_group;" ::: "memory")
#define CP_WAIT1()  asm volatile("cp.async.wait_group 1;" ::: "memory")
#define CP_WAIT0()  asm volatile("cp.async.wait_group 0;" ::: "memory")

// ================= scratch (device globals) =================
__device__ float g_x1  [ROWS*DD];
__device__ float g_x2  [ROWS*DD];

__device__ __nv_bfloat16 g_hbf   [ROWS*DD];
__device__ __nv_bfloat16 g_qkvbf [ROWS*QKVS];
__device__ __nv_bfloat16 g_qbf   [ROWS*DD];
__device__ __nv_bfloat16 g_attnbf[ROWS*DD];
__device__ __nv_bfloat16 g_ffbf  [ROWS*FFF];
__device__ __nv_bfloat16 g_ctxbf [CROWS*CDD];
__device__ __nv_bfloat16 g_kvcbf [CROWS*KVS];
__device__ __nv_bfloat16 g_wqkvt [QKVS*DD];     // [q|k|v] each 640x640
__device__ __nv_bfloat16 g_wo1t  [DD*DD];
__device__ __nv_bfloat16 g_wq2t  [DD*DD];
__device__ __nv_bfloat16 g_wkv2t [KVS*CDD];     // [k|v] each 640x768
__device__ __nv_bfloat16 g_wo2t  [DD*DD];
__device__ __nv_bfloat16 g_wff1t [2*FFF*DD];
__device__ __nv_bfloat16 g_wff2t [DD*FFF];

// ================= weight transpose f32 -> bf16 : W[K,N] -> Wt[N,K] ==========
__global__ void wtrans_kernel(const float* __restrict__ W, __nv_bfloat16* __restrict__ Wt,
                              int K, int N) {
    __shared__ float tsm[32][33];
    int k0 = blockIdx.y * 32, n0 = blockIdx.x * 32;
    tsm[threadIdx.y][threadIdx.x] = W[(size_t)(k0 + threadIdx.y) * N + n0 + threadIdx.x];
    __syncthreads();
    Wt[(size_t)(n0 + threadIdx.y) * K + k0 + threadIdx.x] = __float2bfloat16(tsm[threadIdx.x][threadIdx.y]);
}

__global__ void f2b_kernel(const float* __restrict__ in, __nv_bfloat16* __restrict__ out, int n4) {
    int i = blockIdx.x * blockDim.x + threadIdx.x;
    if (i >= n4) return;
    float4 v = ((const float4*)in)[i];
    uint2 pk;
    pk.x = packbf2(v.x, v.y);
    pk.y = packbf2(v.z, v.w);
    ((uint2*)out)[i] = pk;
}

// ================= HMMA bf16 GEMM, 2-stage cp.async pipeline =================
// C[M,N] = A[M,K] @ Bt[N,K]^T. 128x128 tile, BK=32, 8 warps (2Mx4N).
// EPI: 0 = fp32 out (+bias/+res opts), 1 = bf16 out, 2 = fused GEGLU
//      (interleaved B rows: even = a-col, odd = g-col; out bf16 [M, FFF]).
template<int ADD_BIAS, int ADD_RES, int EPI>
__global__ __launch_bounds__(256)
void hmma_gemm(const __nv_bfloat16* __restrict__ A, const __nv_bfloat16* __restrict__ Bt,
               const float* __restrict__ bias, const float* __restrict__ res,
               void* __restrict__ Cv, int M, int N, int K) {
    __shared__ __nv_bfloat16 As[2][128][40];
    __shared__ __nv_bfloat16 Bs[2][128][40];
    int tid = threadIdx.x;
    int wid = tid >> 5, lane = tid & 31;
    int wm = wid & 1, wn = wid >> 1;
    int mbase = blockIdx.y * 128;
    int nbase = blockIdx.x * 128;       // EPI<2: B-row base
    int lbase = blockIdx.x * 64;        // EPI==2: logical GEGLU col base

    // per-thread load indices (2 chunks of A, 2 of B per stage)
    int i0 = tid, i1 = tid + 256;
    int ar0 = i0 >> 2, ac0 = i0 & 3, ar1 = i1 >> 2, ac1 = i1 & 3;
    int agr0 = min(mbase + ar0, M - 1);
    int agr1 = min(mbase + ar1, M - 1);
    int bgr0, bgr1;
    if (EPI == 2) {
        bgr0 = (ar0 & 1) ? (FFF + lbase + (ar0 >> 1)) : (lbase + (ar0 >> 1));
        bgr1 = (ar1 & 1) ? (FFF + lbase + (ar1 >> 1)) : (lbase + (ar1 >> 1));
    } else {
        bgr0 = nbase + ar0;
        bgr1 = nbase + ar1;
    }

    float acc[4][4][4];
    #pragma unroll
    for (int a = 0; a < 4; a++)
      #pragma unroll
      for (int b = 0; b < 4; b++)
        #pragma unroll
        for (int c = 0; c < 4; c++) acc[a][b][c] = 0.f;

    const int T = K >> 5;

    // stage-0 prefetch
    {
        CPA16(smaddr(&As[0][ar0][ac0 * 8]), A  + (size_t)agr0 * K + ac0 * 8);
        CPA16(smaddr(&As[0][ar1][ac1 * 8]), A  + (size_t)agr1 * K + ac1 * 8);
        CPA16(smaddr(&Bs[0][ar0][ac0 * 8]), Bt + (size_t)bgr0 * K + ac0 * 8);
        CPA16(smaddr(&Bs[0][ar1][ac1 * 8]), Bt + (size_t)bgr1 * K + ac1 * 8);
        CP_COMMIT();
    }

    int mi = lane >> 3, wr = lane & 7;
    for (int t = 0; t < T; t++) {
        int cur = t & 1;
        if (t + 1 < T) {
            int kt = (t + 1) << 5;
            int nx = cur ^ 1;
            CPA16(smaddr(&As[nx][ar0][ac0 * 8]), A  + (size_t)agr0 * K + kt + ac0 * 8);
            CPA16(smaddr(&As[nx][ar1][ac1 * 8]), A  + (size_t)agr1 * K + kt + ac1 * 8);
            CPA16(smaddr(&Bs[nx][ar0][ac0 * 8]), Bt + (size_t)bgr0 * K + kt + ac0 * 8);
            CPA16(smaddr(&Bs[nx][ar1][ac1 * 8]), Bt + (size_t)bgr1 * K + kt + ac1 * 8);
            CP_COMMIT();
            CP_WAIT1();
        } else {
            CP_WAIT0();
        }
        __syncthreads();

        #pragma unroll
        for (int ks = 0; ks < 2; ks++) {
            int k16 = ks * 16;
            uint32_t af[4][4];
            #pragma unroll
            for (int mt = 0; mt < 4; mt++)
                ldsm4(af[mt], smaddr(&As[cur][wm * 64 + mt * 16 + (lane & 15)][k16 + 8 * (lane >> 4)]));
            uint32_t bf[2][4];
            #pragma unroll
            for (int p = 0; p < 2; p++)
                ldsm4(bf[p], smaddr(&Bs[cur][wn * 32 + p * 16 + (mi >> 1) * 8 + wr][k16 + (mi & 1) * 8]));
            #pragma unroll
            for (int mt = 0; mt < 4; mt++)
              #pragma unroll
              for (int nt = 0; nt < 4; nt++)
                mma16816(acc[mt][nt], af[mt], bf[nt >> 1][(nt & 1) * 2], bf[nt >> 1][(nt & 1) * 2 + 1]);
        }
        __syncthreads();
    }

    // ---- epilogue ----
    if (EPI == 2) {
        const float ic = 0.70710678118654752f;
        #pragma unroll
        for (int mt = 0; mt < 4; mt++) {
            int rb = mbase + wm * 64 + mt * 16 + (lane >> 2);
            #pragma unroll
            for (int half = 0; half < 2; half++) {
                int r = rb + half * 8;
                #pragma unroll
                for (int nt = 0; nt < 4; nt++) {
                    int lc = lbase + wn * 16 + nt * 4 + (lane & 3);
                    float av = acc[mt][nt][half * 2 + 0] + bias[lc];
                    float gv = acc[mt][nt][half * 2 + 1] + bias[FFF + lc];
                    float ff = av * 0.5f * gv * (1.f + erff(gv * ic));
                    ((__nv_bfloat16*)Cv)[(size_t)r * FFF + lc] = __float2bfloat16(ff);
                }
            }
        }
    } else {
        #pragma unroll
        for (int mt = 0; mt < 4; mt++) {
            int rb = mbase + wm * 64 + mt * 16 + (lane >> 2);
            #pragma unroll
            for (int half = 0; half < 2; half++) {
                int r = rb + half * 8;
                if (r >= M) continue;
                #pragma unroll
                for (int nt = 0; nt < 4; nt++) {
                    int c = nbase + wn * 32 + nt * 8 + (lane & 3) * 2;
                    float v0 = acc[mt][nt][half * 2 + 0];
                    float v1 = acc[mt][nt][half * 2 + 1];
                    if (ADD_BIAS) { v0 += bias[c]; v1 += bias[c + 1]; }
                    if (ADD_RES) {
                        float2 rv = *(const float2*)&res[(size_t)r * N + c];
                        v0 += rv.x; v1 += rv.y;
                    }
                    if (EPI == 1) {
                        *(uint32_t*)((__nv_bfloat16*)Cv + (size_t)r * N + c) = packbf2(v0, v1);
                    } else {
                        *(float2*)((float*)Cv + (size_t)r * N + c) = make_float2(v0, v1);
                    }
                }
            }
        }
    }
}

// ================= LayerNorm (fp32 in, bf16 out) =================
__global__ void ln_kernel(const float* __restrict__ x,
                          const float* __restrict__ w,
                          const float* __restrict__ b,
                          __nv_bfloat16* __restrict__ out) {
    __shared__ float red[2][8];
    int row = blockIdx.x;
    int tid = threadIdx.x;          // 160 threads
    const float* xr = x + (size_t)row * DD;
    float4 v = *(const float4*)&xr[tid * 4];
    float s  = v.x + v.y + v.z + v.w;
    float sq = v.x*v.x + v.y*v.y + v.z*v.z + v.w*v.w;
    for (int o = 16; o > 0; o >>= 1) {
        s  += __shfl_down_sync(0xffffffffu, s,  o);
        sq += __shfl_down_sync(0xffffffffu, sq, o);
    }
    int wid = tid >> 5, lane = tid & 31;
    if (lane == 0) { red[0][wid] = s; red[1][wid] = sq; }
    __syncthreads();
    if (tid == 0) {
        float S = 0.f, Q = 0.f;
        for (int i = 0; i < 5; i++) { S += red[0][i]; Q += red[1][i]; }
        float mean = S / (float)DD;
        float var  = Q / (float)DD - mean * mean;
        red[0][0] = mean;
        red[1][0] = rsqrtf(var + 1e-5f);
    }
    __syncthreads();
    float mean = red[0][0], inv = red[1][0];
    float4 wv = *(const float4*)&w[tid * 4];
    float4 bv = *(const float4*)&b[tid * 4];
    float o0 = (v.x - mean) * inv * wv.x + bv.x;
    float o1 = (v.y - mean) * inv * wv.y + bv.y;
    float o2 = (v.z - mean) * inv * wv.z + bv.z;
    float o3 = (v.w - mean) * inv * wv.w + bv.w;
    uint2 pk;
    pk.x = packbf2(o0, o1);
    pk.y = packbf2(o2, o3);
    *(uint2*)&out[(size_t)row * DD + tid * 4] = pk;
}

// ================= HMMA flash self-attention, cp.async pipelined =============
// Block: 64 queries x one (b,h), 4 warps (16 q-rows each). Q frags hoisted to
// registers; K/V 64-key chunks double-buffered via cp.async.
#define ATT_PAD 88
#define ATT_SMEM ((64*ATT_PAD + 2*64*ATT_PAD + 2*64*ATT_PAD) * 2)
__global__ __launch_bounds__(128)
void self_attn_hmma(const __nv_bfloat16* __restrict__ qkv, __nv_bfloat16* __restrict__ out) {
    extern __shared__ char smem_[];
    __nv_bfloat16* Qs = (__nv_bfloat16*)smem_;   // [64][88]
    __nv_bfloat16* Ks = Qs + 64 * ATT_PAD;       // [2][64][88]
    __nv_bfloat16* Vs = Ks + 2 * 64 * ATT_PAD;   // [2][64][88]

    int bh = blockIdx.y;
    int b = bh >> 3, h = bh & 7;
    int qbase = blockIdx.x * 64;
    const __nv_bfloat16* qp = qkv + (size_t)b * NN * QKVS + h * DHD;
    const __nv_bfloat16* kp = qp + 640;
    const __nv_bfloat16* vp = qp + 1280;

    int tid = threadIdx.x, wid = tid >> 5, lane = tid & 31;
    int mi = lane >> 3, wr = lane & 7;

    for (int i = tid; i < 64 * 10; i += 128) {
        int r = i / 10, c = i % 10;
        *(uint4*)&Qs[r * ATT_PAD + c * 8] = *(const uint4*)(qp + (size_t)(qbase + r) * QKVS + c * 8);
    }
    // prefetch K/V chunk 0
    for (int i = tid; i < 64 * 10; i += 128) {
        int r = i / 10, c = i % 10;
        CPA16(smaddr(Ks + r * ATT_PAD + c * 8), kp + (size_t)r * QKVS + c * 8);
        CPA16(smaddr(Vs + r * ATT_PAD + c * 8), vp + (size_t)r * QKVS + c * 8);
    }
    CP_COMMIT();
    __syncthreads();

    // hoist Q fragments (warp-invariant across all key chunks)
    uint32_t afq[5][4];
    #pragma unroll
    for (int ks = 0; ks < 5; ks++)
        ldsm4(afq[ks], smaddr(&Qs[(wid * 16 + (lane & 15)) * ATT_PAD + ks * 16 + 8 * (lane >> 4)]));

    float m0 = -1e30f, m1 = -1e30f, l0 = 0.f, l1 = 0.f;
    float oacc[10][4];
    #pragma unroll
    for (int t = 0; t < 10; t++)
      #pragma unroll
      for (int c = 0; c < 4; c++) oacc[t][c] = 0.f;
    const float scale = 0.11180339887498949f;   // 80^-0.5

    const int NCH = NN / 64;    // 64 chunks
    for (int ch = 0; ch < NCH; ch++) {
        int cur = ch & 1;
        if (ch + 1 < NCH) {
            int nx = cur ^ 1;
            int kb = (ch + 1) * 64;
            for (int i = tid; i < 64 * 10; i += 128) {
                int r = i / 10, c = i % 10;
                CPA16(smaddr(Ks + (nx * 64 + r) * ATT_PAD + c * 8), kp + (size_t)(kb + r) * QKVS + c * 8);
                CPA16(smaddr(Vs + (nx * 64 + r) * ATT_PAD + c * 8), vp + (size_t)(kb + r) * QKVS + c * 8);
            }
            CP_COMMIT();
            CP_WAIT1();
        } else {
            CP_WAIT0();
        }
        __syncthreads();
        const __nv_bfloat16* Kc = Ks + cur * 64 * ATT_PAD;
        const __nv_bfloat16* Vc = Vs + cur * 64 * ATT_PAD;

        // ---- S = Q K^T ----
        float s[8][4];
        #pragma unroll
        for (int t = 0; t < 8; t++)
          #pragma unroll
          for (int c = 0; c < 4; c++) s[t][c] = 0.f;
        #pragma unroll
        for (int ks = 0; ks < 5; ks++) {
            #pragma unroll
            for (int p = 0; p < 4; p++) {
                uint32_t bf[4];
                ldsm4(bf, smaddr(&Kc[(p * 16 + (mi >> 1) * 8 + wr) * ATT_PAD + ks * 16 + (mi & 1) * 8]));
                mma16816(s[p * 2 + 0], afq[ks], bf[0], bf[1]);
                mma16816(s[p * 2 + 1], afq[ks], bf[2], bf[3]);
            }
        }

        // ---- online softmax ----
        float rmax0 = -1e30f, rmax1 = -1e30f;
        #pragma unroll
        for (int t = 0; t < 8; t++) {
            s[t][0] *= scale; s[t][1] *= scale; s[t][2] *= scale; s[t][3] *= scale;
            rmax0 = fmaxf(rmax0, fmaxf(s[t][0], s[t][1]));
            rmax1 = fmaxf(rmax1, fmaxf(s[t][2], s[t][3]));
        }
        rmax0 = fmaxf(rmax0, __shfl_xor_sync(0xffffffffu, rmax0, 1));
        rmax0 = fmaxf(rmax0, __shfl_xor_sync(0xffffffffu, rmax0, 2));
        rmax1 = fmaxf(rmax1, __shfl_xor_sync(0xffffffffu, rmax1, 1));
        rmax1 = fmaxf(rmax1, __shfl_xor_sync(0xffffffffu, rmax1, 2));
        float nm0 = fmaxf(m0, rmax0), nm1 = fmaxf(m1, rmax1);
        float alpha0 = __expf(m0 - nm0), alpha1 = __expf(m1 - nm1);
        float sum0 = 0.f, sum1 = 0.f;
        #pragma unroll
        for (int t = 0; t < 8; t++) {
            s[t][0] = __expf(s[t][0] - nm0);
            s[t][1] = __expf(s[t][1] - nm0);
            s[t][2] = __expf(s[t][2] - nm1);
            s[t][3] = __expf(s[t][3] - nm1);
            sum0 += s[t][0] + s[t][1];
            sum1 += s[t][2] + s[t][3];
        }
        sum0 += __shfl_xor_sync(0xffffffffu, sum0, 1);
        sum0 += __shfl_xor_sync(0xffffffffu, sum0, 2);
        sum1 += __shfl_xor_sync(0xffffffffu, sum1, 1);
        sum1 += __shfl_xor_sync(0xffffffffu, sum1, 2);
        m0 = nm0; m1 = nm1;
        l0 = l0 * alpha0 + sum0;
        l1 = l1 * alpha1 + sum1;
        #pragma unroll
        for (int t = 0; t < 10; t++) {
            oacc[t][0] *= alpha0; oacc[t][1] *= alpha0;
            oacc[t][2] *= alpha1; oacc[t][3] *= alpha1;
        }

        // ---- P -> A-frags (register repack) ----
        uint32_t pf[4][4];
        #pragma unroll
        for (int g = 0; g < 4; g++) {
            pf[g][0] = packbf2(s[2*g][0],   s[2*g][1]);
            pf[g][1] = packbf2(s[2*g][2],   s[2*g][3]);
            pf[g][2] = packbf2(s[2*g+1][0], s[2*g+1][1]);
            pf[g][3] = packbf2(s[2*g+1][2], s[2*g+1][3]);
        }
        // ---- O += P V ----
        #pragma unroll
        for (int g = 0; g < 4; g++) {
            #pragma unroll
            for (int p = 0; p < 5; p++) {
                uint32_t bf[4];
                ldsm4t(bf, smaddr(&Vc[(g * 16 + (mi & 1) * 8 + wr) * ATT_PAD + p * 16 + (mi >> 1) * 8]));
                mma16816(oacc[p * 2 + 0], pf[g], bf[0], bf[1]);
                mma16816(oacc[p * 2 + 1], pf[g], bf[2], bf[3]);
            }
        }
        __syncthreads();
    }

    float inv0 = 1.f / l0, inv1 = 1.f / l1;
    int r0 = qbase + wid * 16 + (lane >> 2);
    __nv_bfloat16* op = out + (size_t)b * NN * DD + h * DHD;
    #pragma unroll
    for (int t = 0; t < 10; t++) {
        int d = t * 8 + (lane & 3) * 2;
        *(uint32_t*)(op + (size_t)r0 * DD + d)       = packbf2(oacc[t][0] * inv0, oacc[t][1] * inv0);
        *(uint32_t*)(op + (size_t)(r0 + 8) * DD + d) = packbf2(oacc[t][2] * inv1, oacc[t][3] * inv1);
    }
}

// ================= Cross attention (77 keys; bf16 I/O, fp32 inside) ==========
#define CA_SMEM ((64*80 + 77*80 + 77*80 + 64*80 + 64) * 4)
__global__ __launch_bounds__(256)
void cross_attn_kernel(const __nv_bfloat16* __restrict__ q, const __nv_bfloat16* __restrict__ kvc,
                       __nv_bfloat16* __restrict__ out) {
    extern __shared__ float sm[];
    float* Qs = sm;
    float* Ks = Qs + 64 * 80;
    float* Vs = Ks + 77 * 80;
    float* Ss = Vs + 77 * 80;
    float* lrow = Ss + 64 * 80;

    int bh = blockIdx.y;
    int b = bh >> 3, h = bh & 7;
    int qbase = blockIdx.x * 64;
    const __nv_bfloat16* qp = q   + (size_t)b * NN * DD   + h * DHD;
    const __nv_bfloat16* kp = kvc + (size_t)b * CNN * KVS + h * DHD;
    const __nv_bfloat16* vp = kp + 640;

    int tid = threadIdx.x;
    for (int i = tid; i < 64 * 80; i += 256) {
        int r = i / 80, d = i % 80;
        Qs[i] = __bfloat162float(qp[(size_t)(qbase + r) * DD + d]);
    }
    for (int i = tid; i < 77 * 80; i += 256) {
        int r = i / 80, d = i % 80;
        Ks[i] = __bfloat162float(kp[(size_t)r * KVS + d]);
        Vs[i] = __bfloat162float(vp[(size_t)r * KVS + d]);
    }
    __syncthreads();

    int rr = tid >> 2, cc = tid & 3;
    const float scale = 0.11180339887498949f;

    float mx = -1e30f;
    for (int j = cc; j < CNN; j += 4) {
        const float* qrow = &Qs[rr * 80];
        const float* krow = &Ks[j * 80];
        float s = 0.f;
        #pragma unroll
        for (int d4 = 0; d4 < 20; d4++) {
            float4 a  = *(const float4*)&qrow[d4 * 4];
            float4 kk = *(const float4*)&krow[d4 * 4];
            s += a.x*kk.x + a.y*kk.y + a.z*kk.z + a.w*kk.w;
        }
        s *= scale;
        Ss[rr * 80 + j] = s;
        mx = fmaxf(mx, s);
    }
    mx = fmaxf(mx, __shfl_xor_sync(0xffffffffu, mx, 1));
    mx = fmaxf(mx, __shfl_xor_sync(0xffffffffu, mx, 2));
    float sum = 0.f;
    for (int j = cc; j < CNN; j += 4) {
        float p = __expf(Ss[rr * 80 + j] - mx);
        Ss[rr * 80 + j] = p;
        sum += p;
    }
    sum += __shfl_xor_sync(0xffffffffu, sum, 1);
    sum += __shfl_xor_sync(0xffffffffu, sum, 2);
    if (cc == 0) lrow[rr] = sum;
    __syncwarp();

    float o[20];
    #pragma unroll
    for (int i = 0; i < 20; i++) o[i] = 0.f;
    for (int j = 0; j < CNN; j++) {
        float p = Ss[rr * 80 + j];
        const float* vrow = &Vs[j * 80 + cc * 20];
        #pragma unroll
        for (int i4 = 0; i4 < 5; i4++) {
            float4 vv = *(const float4*)&vrow[i4 * 4];
            o[i4*4+0] += p * vv.x;
            o[i4*4+1] += p * vv.y;
            o[i4*4+2] += p * vv.z;
            o[i4*4+3] += p * vv.w;
        }
    }
    float inv = 1.0f / lrow[rr];
    __nv_bfloat16* op = out + (size_t)b * NN * DD + h * DHD
                            + (size_t)(qbase + rr) * DD + cc * 20;
    #pragma unroll
    for (int i2 = 0; i2 < 10; i2++) {
        *(uint32_t*)(op + i2 * 2) = packbf2(o[i2*2+0] * inv, o[i2*2+1] * inv);
    }
}

// ================= launch =================
extern "C" void kernel_launch(void* const* d_in, const int* in_sizes, int n_in,
                              void* d_out, int out_size) {
    const float* x       = (const float*)d_in[0];
    const float* context = (const float*)d_in[1];
    const float* ln1_w = (const float*)d_in[2];
    const float* ln1_b = (const float*)d_in[3];
    const float* ln2_w = (const float*)d_in[4];
    const float* ln2_b = (const float*)d_in[5];
    const float* ln3_w = (const float*)d_in[6];
    const float* ln3_b = (const float*)d_in[7];
    const float* wq1 = (const float*)d_in[8];
    const float* wk1 = (const float*)d_in[9];
    const float* wv1 = (const float*)d_in[10];
    const float* wo1 = (const float*)d_in[11];
    const float* bo1 = (const float*)d_in[12];
    const float* wq2 = (const float*)d_in[13];
    const float* wk2 = (const float*)d_in[14];
    const float* wv2 = (const float*)d_in[15];
    const float* wo2 = (const float*)d_in[16];
    const float* bo2 = (const float*)d_in[17];
    const float* w_ff1 = (const float*)d_in[18];
    const float* b_ff1 = (const float*)d_in[19];
    const float* w_ff2 = (const float*)d_in[20];
    const float* b_ff2 = (const float*)d_in[21];
    float* out = (float*)d_out;

    float *x1, *x2;
    __nv_bfloat16 *hbf, *qkvbf, *qbf, *attnbf, *ffbf, *ctxbf, *kvcbf;
    __nv_bfloat16 *wqkvt, *wo1t, *wq2t, *wkv2t, *wo2t, *wff1t, *wff2t;
    cudaGetSymbolAddress((void**)&x1, g_x1);
    cudaGetSymbolAddress((void**)&x2, g_x2);
    cudaGetSymbolAddress((void**)&hbf, g_hbf);
    cudaGetSymbolAddress((void**)&qkvbf, g_qkvbf);
    cudaGetSymbolAddress((void**)&qbf, g_qbf);
    cudaGetSymbolAddress((void**)&attnbf, g_attnbf);
    cudaGetSymbolAddress((void**)&ffbf, g_ffbf);
    cudaGetSymbolAddress((void**)&ctxbf, g_ctxbf);
    cudaGetSymbolAddress((void**)&kvcbf, g_kvcbf);
    cudaGetSymbolAddress((void**)&wqkvt, g_wqkvt);
    cudaGetSymbolAddress((void**)&wo1t, g_wo1t);
    cudaGetSymbolAddress((void**)&wq2t, g_wq2t);
    cudaGetSymbolAddress((void**)&wkv2t, g_wkv2t);
    cudaGetSymbolAddress((void**)&wo2t, g_wo2t);
    cudaGetSymbolAddress((void**)&wff1t, g_wff1t);
    cudaGetSymbolAddress((void**)&wff2t, g_wff2t);

    cudaFuncSetAttribute(self_attn_hmma,    cudaFuncAttributeMaxDynamicSharedMemorySize, ATT_SMEM);
    cudaFuncSetAttribute(cross_attn_kernel, cudaFuncAttributeMaxDynamicSharedMemorySize, CA_SMEM);

    dim3 tb(32, 32);
    wtrans_kernel<<<dim3(DD/32, DD/32), tb>>>(wq1, wqkvt, DD, DD);
    wtrans_kernel<<<dim3(DD/32, DD/32), tb>>>(wk1, wqkvt + DD*DD, DD, DD);
    wtrans_kernel<<<dim3(DD/32, DD/32), tb>>>(wv1, wqkvt + 2*DD*DD, DD, DD);
    wtrans_kernel<<<dim3(DD/32, DD/32), tb>>>(wo1, wo1t, DD, DD);
    wtrans_kernel<<<dim3(DD/32, DD/32), tb>>>(wq2, wq2t, DD, DD);
    wtrans_kernel<<<dim3(DD/32, CDD/32), tb>>>(wk2, wkv2t, CDD, DD);
    wtrans_kernel<<<dim3(DD/32, CDD/32), tb>>>(wv2, wkv2t + DD*CDD, CDD, DD);
    wtrans_kernel<<<dim3(DD/32, DD/32), tb>>>(wo2, wo2t, DD, DD);
    wtrans_kernel<<<dim3(2*FFF/32, DD/32), tb>>>(w_ff1, wff1t, DD, 2*FFF);
    wtrans_kernel<<<dim3(DD/32, FFF/32), tb>>>(w_ff2, wff2t, FFF, DD);
    f2b_kernel<<<(CROWS*CDD/4 + 255)/256, 256>>>(context, ctxbf, CROWS*CDD/4);

    dim3 gqkv(QKVS/128, ROWS/128);          // (15, 64)
    dim3 g640(DD/128, ROWS/128);            // (5, 64)
    dim3 gff1(FFF/64, ROWS/128);            // (40, 64)
    dim3 gkvc(KVS/128, (CROWS + 127)/128);  // (10, 2)
    dim3 gattn(NN/64, BB*HH);               // (64, 16)

    // ----- self-attention block -----
    ln_kernel<<<ROWS, 160>>>(x, ln1_w, ln1_b, hbf);
    hmma_gemm<0,0,1><<<gqkv, 256>>>(hbf, wqkvt, nullptr, nullptr, qkvbf, ROWS, QKVS, DD);
    self_attn_hmma<<<gattn, 128, ATT_SMEM>>>(qkvbf, attnbf);
    hmma_gemm<1,1,0><<<g640, 256>>>(attnbf, wo1t, bo1, x, x1, ROWS, DD, DD);

    // ----- cross-attention block -----
    ln_kernel<<<ROWS, 160>>>(x1, ln2_w, ln2_b, hbf);
    hmma_gemm<0,0,1><<<g640, 256>>>(hbf, wq2t, nullptr, nullptr, qbf, ROWS, DD, DD);
    hmma_gemm<0,0,1><<<gkvc, 256>>>(ctxbf, wkv2t, nullptr, nullptr, kvcbf, CROWS, KVS, CDD);
    cross_attn_kernel<<<gattn, 256, CA_SMEM>>>(qbf, kvcbf, attnbf);
    hmma_gemm<1,1,0><<<g640, 256>>>(attnbf, wo2t, bo2, x1, x2, ROWS, DD, DD);

    // ----- GEGLU FF block (geglu fused into FF1 epilogue) -----
    ln_kernel<<<ROWS, 160>>>(x2, ln3_w, ln3_b, hbf);
    hmma_gemm<1,0,2><<<gff1, 256>>>(hbf, wff1t, b_ff1, nullptr, ffbf, ROWS, FFF, DD);
    hmma_gemm<1,1,0><<<g640, 256>>>(ffbf, wff2t, b_ff2, x2, out, ROWS, DD, FFF);
}

// round 7
// speedup vs baseline: 7.1109x; 1.0211x over previous
#include <cuda_runtime.h>
#include <cuda_bf16.h>
#include <math.h>
#include <cstdint>

// Problem dims
#define BB   2
#define NN   4096
#define DD   640
#define HH   8
#define DHD  80
#define CNN  77
#define CDD  768
#define FFF  2560
#define ROWS (BB*NN)          // 8192
#define CROWS (BB*CNN)        // 154
#define QKVS 1920             // fused qkv row stride
#define KVS  1280             // fused ctx k/v row stride

// ================= mma.sync / ldmatrix / cp.async helpers ====================
__device__ __forceinline__ void ldsm4(uint32_t* r, uint32_t addr) {
    asm volatile("ldmatrix.sync.aligned.m8n8.x4.shared.b16 {%0,%1,%2,%3}, [%4];"
        : "=r"(r[0]), "=r"(r[1]), "=r"(r[2]), "=r"(r[3]) : "r"(addr));
}
__device__ __forceinline__ void ldsm4t(uint32_t* r, uint32_t addr) {
    asm volatile("ldmatrix.sync.aligned.m8n8.x4.trans.shared.b16 {%0,%1,%2,%3}, [%4];"
        : "=r"(r[0]), "=r"(r[1]), "=r"(r[2]), "=r"(r[3]) : "r"(addr));
}
__device__ __forceinline__ void mma16816(float* c, const uint32_t* a, uint32_t b0, uint32_t b1) {
    asm volatile("mma.sync.aligned.m16n8k16.row.col.f32.bf16.bf16.f32 "
        "{%0,%1,%2,%3}, {%4,%5,%6,%7}, {%8,%9}, {%0,%1,%2,%3};"
        : "+f"(c[0]), "+f"(c[1]), "+f"(c[2]), "+f"(c[3])
        : "r"(a[0]), "r"(a[1]), "r"(a[2]), "r"(a[3]), "r"(b0), "r"(b1));
}
__device__ __forceinline__ uint32_t smaddr(const void* p) {
    return (uint32_t)__cvta_generic_to_shared(p);
}
__device__ __forceinline__ uint32_t packbf2(float lo, float hi) {
    __nv_bfloat162 t = __floats2bfloat162_rn(lo, hi);
    return *(uint32_t*)&t;
}
#define CPA16(dst, src) \
    asm volatile("cp.async.cg.shared.global [%0], [%1], 16;" :: "r"(dst), "l"(src))
#define CP_COMMIT() asm volatile("cp.async.commit_group;" ::: "memory")
#define CP_WAIT1()  asm volatile("cp.async.wait_group 1;" ::: "memory")
#define CP_WAIT0()  asm volatile("cp.async.wait_group 0;" ::: "memory")

// ================= scratch (device globals) =================
__device__ float g_x1  [ROWS*DD];
__device__ float g_x2  [ROWS*DD];

__device__ __nv_bfloat16 g_hbf   [ROWS*DD];
__device__ __nv_bfloat16 g_qkvbf [ROWS*QKVS];
__device__ __nv_bfloat16 g_qbf   [ROWS*DD];
__device__ __nv_bfloat16 g_attnbf[ROWS*DD];
__device__ __nv_bfloat16 g_ffbf  [ROWS*FFF];
__device__ __nv_bfloat16 g_ctxbf [CROWS*CDD];
__device__ __nv_bfloat16 g_kvcbf [CROWS*KVS];
__device__ __nv_bfloat16 g_wqkvt [QKVS*DD];
__device__ __nv_bfloat16 g_wo1t  [DD*DD];
__device__ __nv_bfloat16 g_wq2t  [DD*DD];
__device__ __nv_bfloat16 g_wkv2t [KVS*CDD];
__device__ __nv_bfloat16 g_wo2t  [DD*DD];
__device__ __nv_bfloat16 g_wff1t [2*FFF*DD];
__device__ __nv_bfloat16 g_wff2t [DD*FFF];

// ================= weight transpose f32 -> bf16 : W[K,N] -> Wt[N,K] ==========
__global__ void wtrans_kernel(const float* __restrict__ W, __nv_bfloat16* __restrict__ Wt,
                              int K, int N) {
    __shared__ float tsm[32][33];
    int k0 = blockIdx.y * 32, n0 = blockIdx.x * 32;
    tsm[threadIdx.y][threadIdx.x] = W[(size_t)(k0 + threadIdx.y) * N + n0 + threadIdx.x];
    __syncthreads();
    Wt[(size_t)(n0 + threadIdx.y) * K + k0 + threadIdx.x] = __float2bfloat16(tsm[threadIdx.x][threadIdx.y]);
}

__global__ void f2b_kernel(const float* __restrict__ in, __nv_bfloat16* __restrict__ out, int n4) {
    int i = blockIdx.x * blockDim.x + threadIdx.x;
    if (i >= n4) return;
    float4 v = ((const float4*)in)[i];
    uint2 pk;
    pk.x = packbf2(v.x, v.y);
    pk.y = packbf2(v.z, v.w);
    ((uint2*)out)[i] = pk;
}

// ================= HMMA bf16 GEMM, 3-stage cp.async pipeline =================
// C[M,N] = A[M,K] @ Bt[N,K]^T. 128x128 tile, BK=32, 8 warps (2Mx4N).
// EPI: 0 = fp32 out, 1 = bf16 out, 2 = fused GEGLU (interleaved B rows).
#define GST 3
#define GEMM_DSMEM (GST*2*128*40*2)   // 61440 B
template<int ADD_BIAS, int ADD_RES, int EPI>
__global__ __launch_bounds__(256)
void hmma_gemm(const __nv_bfloat16* __restrict__ A, const __nv_bfloat16* __restrict__ Bt,
               const float* __restrict__ bias, const float* __restrict__ res,
               void* __restrict__ Cv, int M, int N, int K) {
    extern __shared__ __nv_bfloat16 dsm[];
    __nv_bfloat16* Asm = dsm;                   // [GST][128][40]
    __nv_bfloat16* Bsm = dsm + GST * 128 * 40;  // [GST][128][40]
    int tid = threadIdx.x;
    int wid = tid >> 5, lane = tid & 31;
    int wm = wid & 1, wn = wid >> 1;
    int mbase = blockIdx.y * 128;
    int nbase = blockIdx.x * 128;
    int lbase = blockIdx.x * 64;

    int i0 = tid, i1 = tid + 256;
    int ar0 = i0 >> 2, ac0 = i0 & 3, ar1 = i1 >> 2, ac1 = i1 & 3;
    int agr0 = min(mbase + ar0, M - 1);
    int agr1 = min(mbase + ar1, M - 1);
    int bgr0, bgr1;
    if (EPI == 2) {
        bgr0 = (ar0 & 1) ? (FFF + lbase + (ar0 >> 1)) : (lbase + (ar0 >> 1));
        bgr1 = (ar1 & 1) ? (FFF + lbase + (ar1 >> 1)) : (lbase + (ar1 >> 1));
    } else {
        bgr0 = nbase + ar0;
        bgr1 = nbase + ar1;
    }

    float acc[4][4][4];
    #pragma unroll
    for (int a = 0; a < 4; a++)
      #pragma unroll
      for (int b = 0; b < 4; b++)
        #pragma unroll
        for (int c = 0; c < 4; c++) acc[a][b][c] = 0.f;

    const int T = K >> 5;

    // prefetch stages 0..GST-2
    #pragma unroll
    for (int s = 0; s < GST - 1; s++) {
        int kt = s * 32;
        __nv_bfloat16* as = Asm + s * 5120;
        __nv_bfloat16* bs = Bsm + s * 5120;
        CPA16(smaddr(as + ar0 * 40 + ac0 * 8), A  + (size_t)agr0 * K + kt + ac0 * 8);
        CPA16(smaddr(as + ar1 * 40 + ac1 * 8), A  + (size_t)agr1 * K + kt + ac1 * 8);
        CPA16(smaddr(bs + ar0 * 40 + ac0 * 8), Bt + (size_t)bgr0 * K + kt + ac0 * 8);
        CPA16(smaddr(bs + ar1 * 40 + ac1 * 8), Bt + (size_t)bgr1 * K + kt + ac1 * 8);
        CP_COMMIT();
    }

    int mi = lane >> 3, wr = lane & 7;
    int cur = 0, nxt = GST - 1;
    for (int t = 0; t < T; t++) {
        if (t == T - 1) { CP_WAIT0(); } else { CP_WAIT1(); }
        __syncthreads();

        const __nv_bfloat16* as = Asm + cur * 5120;
        const __nv_bfloat16* bs = Bsm + cur * 5120;
        #pragma unroll
        for (int ks = 0; ks < 2; ks++) {
            int k16 = ks * 16;
            uint32_t af[4][4];
            #pragma unroll
            for (int mt = 0; mt < 4; mt++)
                ldsm4(af[mt], smaddr(as + (wm * 64 + mt * 16 + (lane & 15)) * 40 + k16 + 8 * (lane >> 4)));
            uint32_t bf[2][4];
            #pragma unroll
            for (int p = 0; p < 2; p++)
                ldsm4(bf[p], smaddr(bs + (wn * 32 + p * 16 + (mi >> 1) * 8 + wr) * 40 + k16 + (mi & 1) * 8));
            #pragma unroll
            for (int mt = 0; mt < 4; mt++)
              #pragma unroll
              for (int nt = 0; nt < 4; nt++)
                mma16816(acc[mt][nt], af[mt], bf[nt >> 1][(nt & 1) * 2], bf[nt >> 1][(nt & 1) * 2 + 1]);
        }

        int pt = t + GST - 1;
        if (pt < T) {
            int kt = pt << 5;
            __nv_bfloat16* al = Asm + nxt * 5120;
            __nv_bfloat16* bl = Bsm + nxt * 5120;
            CPA16(smaddr(al + ar0 * 40 + ac0 * 8), A  + (size_t)agr0 * K + kt + ac0 * 8);
            CPA16(smaddr(al + ar1 * 40 + ac1 * 8), A  + (size_t)agr1 * K + kt + ac1 * 8);
            CPA16(smaddr(bl + ar0 * 40 + ac0 * 8), Bt + (size_t)bgr0 * K + kt + ac0 * 8);
            CPA16(smaddr(bl + ar1 * 40 + ac1 * 8), Bt + (size_t)bgr1 * K + kt + ac1 * 8);
            CP_COMMIT();
        }
        cur = (cur + 1 == GST) ? 0 : cur + 1;
        nxt = (nxt + 1 == GST) ? 0 : nxt + 1;
    }

    // ---- epilogue ----
    if (EPI == 2) {
        const float ic = 0.70710678118654752f;
        #pragma unroll
        for (int mt = 0; mt < 4; mt++) {
            int rb = mbase + wm * 64 + mt * 16 + (lane >> 2);
            #pragma unroll
            for (int half = 0; half < 2; half++) {
                int r = rb + half * 8;
                #pragma unroll
                for (int nt = 0; nt < 4; nt++) {
                    int lc = lbase + wn * 16 + nt * 4 + (lane & 3);
                    float av = acc[mt][nt][half * 2 + 0] + bias[lc];
                    float gv = acc[mt][nt][half * 2 + 1] + bias[FFF + lc];
                    float ff = av * 0.5f * gv * (1.f + erff(gv * ic));
                    ((__nv_bfloat16*)Cv)[(size_t)r * FFF + lc] = __float2bfloat16(ff);
                }
            }
        }
    } else {
        #pragma unroll
        for (int mt = 0; mt < 4; mt++) {
            int rb = mbase + wm * 64 + mt * 16 + (lane >> 2);
            #pragma unroll
            for (int half = 0; half < 2; half++) {
                int r = rb + half * 8;
                if (r >= M) continue;
                #pragma unroll
                for (int nt = 0; nt < 4; nt++) {
                    int c = nbase + wn * 32 + nt * 8 + (lane & 3) * 2;
                    float v0 = acc[mt][nt][half * 2 + 0];
                    float v1 = acc[mt][nt][half * 2 + 1];
                    if (ADD_BIAS) { v0 += bias[c]; v1 += bias[c + 1]; }
                    if (ADD_RES) {
                        float2 rv = *(const float2*)&res[(size_t)r * N + c];
                        v0 += rv.x; v1 += rv.y;
                    }
                    if (EPI == 1) {
                        *(uint32_t*)((__nv_bfloat16*)Cv + (size_t)r * N + c) = packbf2(v0, v1);
                    } else {
                        *(float2*)((float*)Cv + (size_t)r * N + c) = make_float2(v0, v1);
                    }
                }
            }
        }
    }
}

// ================= LayerNorm (fp32 in, bf16 out) =================
__global__ void ln_kernel(const float* __restrict__ x,
                          const float* __restrict__ w,
                          const float* __restrict__ b,
                          __nv_bfloat16* __restrict__ out) {
    __shared__ float red[2][8];
    int row = blockIdx.x;
    int tid = threadIdx.x;          // 160 threads
    const float* xr = x + (size_t)row * DD;
    float4 v = *(const float4*)&xr[tid * 4];
    float s  = v.x + v.y + v.z + v.w;
    float sq = v.x*v.x + v.y*v.y + v.z*v.z + v.w*v.w;
    for (int o = 16; o > 0; o >>= 1) {
        s  += __shfl_down_sync(0xffffffffu, s,  o);
        sq += __shfl_down_sync(0xffffffffu, sq, o);
    }
    int wid = tid >> 5, lane = tid & 31;
    if (lane == 0) { red[0][wid] = s; red[1][wid] = sq; }
    __syncthreads();
    if (tid == 0) {
        float S = 0.f, Q = 0.f;
        for (int i = 0; i < 5; i++) { S += red[0][i]; Q += red[1][i]; }
        float mean = S / (float)DD;
        float var  = Q / (float)DD - mean * mean;
        red[0][0] = mean;
        red[1][0] = rsqrtf(var + 1e-5f);
    }
    __syncthreads();
    float mean = red[0][0], inv = red[1][0];
    float4 wv = *(const float4*)&w[tid * 4];
    float4 bv = *(const float4*)&b[tid * 4];
    float o0 = (v.x - mean) * inv * wv.x + bv.x;
    float o1 = (v.y - mean) * inv * wv.y + bv.y;
    float o2 = (v.z - mean) * inv * wv.z + bv.z;
    float o3 = (v.w - mean) * inv * wv.w + bv.w;
    uint2 pk;
    pk.x = packbf2(o0, o1);
    pk.y = packbf2(o2, o3);
    *(uint2*)&out[(size_t)row * DD + tid * 4] = pk;
}

// ================= HMMA flash self-attention, 3-stage cp.async ===============
// Block: 128 queries x one (b,h), 8 warps (16 q-rows each). Q frags hoisted;
// K/V 64-key chunks triple-buffered; one __syncthreads per chunk.
#define ATT_PAD 88
#define ATT_SMEM ((128*ATT_PAD + 3*64*ATT_PAD + 3*64*ATT_PAD) * 2)
__global__ __launch_bounds__(256)
void self_attn_hmma(const __nv_bfloat16* __restrict__ qkv, __nv_bfloat16* __restrict__ out) {
    extern __shared__ char smem_[];
    __nv_bfloat16* Qs = (__nv_bfloat16*)smem_;   // [128][88]
    __nv_bfloat16* Ks = Qs + 128 * ATT_PAD;      // [3][64][88]
    __nv_bfloat16* Vs = Ks + 3 * 64 * ATT_PAD;   // [3][64][88]

    int bh = blockIdx.y;
    int b = bh >> 3, h = bh & 7;
    int qbase = blockIdx.x * 128;
    const __nv_bfloat16* qp = qkv + (size_t)b * NN * QKVS + h * DHD;
    const __nv_bfloat16* kp = qp + 640;
    const __nv_bfloat16* vp = qp + 1280;

    int tid = threadIdx.x, wid = tid >> 5, lane = tid & 31;
    int mi = lane >> 3, wr = lane & 7;

    // load Q tile (plain stores) + prefetch K/V chunks 0,1
    for (int i = tid; i < 128 * 10; i += 256) {
        int r = i / 10, c = i % 10;
        *(uint4*)&Qs[r * ATT_PAD + c * 8] = *(const uint4*)(qp + (size_t)(qbase + r) * QKVS + c * 8);
    }
    #pragma unroll
    for (int s = 0; s < 2; s++) {
        for (int i = tid; i < 64 * 10; i += 256) {
            int r = i / 10, c = i % 10;
            CPA16(smaddr(Ks + (s * 64 + r) * ATT_PAD + c * 8), kp + (size_t)(s * 64 + r) * QKVS + c * 8);
            CPA16(smaddr(Vs + (s * 64 + r) * ATT_PAD + c * 8), vp + (size_t)(s * 64 + r) * QKVS + c * 8);
        }
        CP_COMMIT();
    }
    __syncthreads();

    // hoist Q fragments
    uint32_t afq[5][4];
    #pragma unroll
    for (int ks = 0; ks < 5; ks++)
        ldsm4(afq[ks], smaddr(&Qs[(wid * 16 + (lane & 15)) * ATT_PAD + ks * 16 + 8 * (lane >> 4)]));

    float m0 = -1e30f, m1 = -1e30f, l0 = 0.f, l1 = 0.f;
    float oacc[10][4];
    #pragma unroll
    for (int t = 0; t < 10; t++)
      #pragma unroll
      for (int c = 0; c < 4; c++) oacc[t][c] = 0.f;
    const float scale = 0.11180339887498949f;   // 80^-0.5

    const int NCH = NN / 64;    // 64 chunks
    int cur = 0, nxt = 2;
    for (int ch = 0; ch < NCH; ch++) {
        if (ch == NCH - 1) { CP_WAIT0(); } else { CP_WAIT1(); }
        __syncthreads();
        const __nv_bfloat16* Kc = Ks + cur * 64 * ATT_PAD;
        const __nv_bfloat16* Vc = Vs + cur * 64 * ATT_PAD;

        // ---- S = Q K^T ----
        float s[8][4];
        #pragma unroll
        for (int t = 0; t < 8; t++)
          #pragma unroll
          for (int c = 0; c < 4; c++) s[t][c] = 0.f;
        #pragma unroll
        for (int ks = 0; ks < 5; ks++) {
            #pragma unroll
            for (int p = 0; p < 4; p++) {
                uint32_t bf[4];
                ldsm4(bf, smaddr(&Kc[(p * 16 + (mi >> 1) * 8 + wr) * ATT_PAD + ks * 16 + (mi & 1) * 8]));
                mma16816(s[p * 2 + 0], afq[ks], bf[0], bf[1]);
                mma16816(s[p * 2 + 1], afq[ks], bf[2], bf[3]);
            }
        }

        // ---- online softmax ----
        float rmax0 = -1e30f, rmax1 = -1e30f;
        #pragma unroll
        for (int t = 0; t < 8; t++) {
            s[t][0] *= scale; s[t][1] *= scale; s[t][2] *= scale; s[t][3] *= scale;
            rmax0 = fmaxf(rmax0, fmaxf(s[t][0], s[t][1]));
            rmax1 = fmaxf(rmax1, fmaxf(s[t][2], s[t][3]));
        }
        rmax0 = fmaxf(rmax0, __shfl_xor_sync(0xffffffffu, rmax0, 1));
        rmax0 = fmaxf(rmax0, __shfl_xor_sync(0xffffffffu, rmax0, 2));
        rmax1 = fmaxf(rmax1, __shfl_xor_sync(0xffffffffu, rmax1, 1));
        rmax1 = fmaxf(rmax1, __shfl_xor_sync(0xffffffffu, rmax1, 2));
        float nm0 = fmaxf(m0, rmax0), nm1 = fmaxf(m1, rmax1);
        float alpha0 = __expf(m0 - nm0), alpha1 = __expf(m1 - nm1);
        float sum0 = 0.f, sum1 = 0.f;
        #pragma unroll
        for (int t = 0; t < 8; t++) {
            s[t][0] = __expf(s[t][0] - nm0);
            s[t][1] = __expf(s[t][1] - nm0);
            s[t][2] = __expf(s[t][2] - nm1);
            s[t][3] = __expf(s[t][3] - nm1);
            sum0 += s[t][0] + s[t][1];
            sum1 += s[t][2] + s[t][3];
        }
        sum0 += __shfl_xor_sync(0xffffffffu, sum0, 1);
        sum0 += __shfl_xor_sync(0xffffffffu, sum0, 2);
        sum1 += __shfl_xor_sync(0xffffffffu, sum1, 1);
        sum1 += __shfl_xor_sync(0xffffffffu, sum1, 2);
        m0 = nm0; m1 = nm1;
        l0 = l0 * alpha0 + sum0;
        l1 = l1 * alpha1 + sum1;
        #pragma unroll
        for (int t = 0; t < 10; t++) {
            oacc[t][0] *= alpha0; oacc[t][1] *= alpha0;
            oacc[t][2] *= alpha1; oacc[t][3] *= alpha1;
        }

        // ---- P -> A-frags (register repack) ----
        uint32_t pf[4][4];
        #pragma unroll
        for (int g = 0; g < 4; g++) {
            pf[g][0] = packbf2(s[2*g][0],   s[2*g][1]);
            pf[g][1] = packbf2(s[2*g][2],   s[2*g][3]);
            pf[g][2] = packbf2(s[2*g+1][0], s[2*g+1][1]);
            pf[g][3] = packbf2(s[2*g+1][2], s[2*g+1][3]);
        }
        // ---- O += P V ----
        #pragma unroll
        for (int g = 0; g < 4; g++) {
            #pragma unroll
            for (int p = 0; p < 5; p++) {
                uint32_t bf[4];
                ldsm4t(bf, smaddr(&Vc[(g * 16 + (mi & 1) * 8 + wr) * ATT_PAD + p * 16 + (mi >> 1) * 8]));
                mma16816(oacc[p * 2 + 0], pf[g], bf[0], bf[1]);
                mma16816(oacc[p * 2 + 1], pf[g], bf[2], bf[3]);
            }
        }

        // prefetch chunk ch+2 into slot nxt (not read until 2 iters later)
        int pc = ch + 2;
        if (pc < NCH) {
            int kb = pc * 64;
            __nv_bfloat16* Kl = Ks + nxt * 64 * ATT_PAD;
            __nv_bfloat16* Vl = Vs + nxt * 64 * ATT_PAD;
            for (int i = tid; i < 64 * 10; i += 256) {
                int r = i / 10, c = i % 10;
                CPA16(smaddr(Kl + r * ATT_PAD + c * 8), kp + (size_t)(kb + r) * QKVS + c * 8);
                CPA16(smaddr(Vl + r * ATT_PAD + c * 8), vp + (size_t)(kb + r) * QKVS + c * 8);
            }
            CP_COMMIT();
        }
        cur = (cur + 1 == 3) ? 0 : cur + 1;
        nxt = (nxt + 1 == 3) ? 0 : nxt + 1;
    }

    float inv0 = 1.f / l0, inv1 = 1.f / l1;
    int r0 = qbase + wid * 16 + (lane >> 2);
    __nv_bfloat16* op = out + (size_t)b * NN * DD + h * DHD;
    #pragma unroll
    for (int t = 0; t < 10; t++) {
        int d = t * 8 + (lane & 3) * 2;
        *(uint32_t*)(op + (size_t)r0 * DD + d)       = packbf2(oacc[t][0] * inv0, oacc[t][1] * inv0);
        *(uint32_t*)(op + (size_t)(r0 + 8) * DD + d) = packbf2(oacc[t][2] * inv1, oacc[t][3] * inv1);
    }
}

// ================= Cross attention (77 keys; bf16 I/O, fp32 inside) ==========
#define CA_SMEM ((64*80 + 77*80 + 77*80 + 64*80 + 64) * 4)
__global__ __launch_bounds__(256)
void cross_attn_kernel(const __nv_bfloat16* __restrict__ q, const __nv_bfloat16* __restrict__ kvc,
                       __nv_bfloat16* __restrict__ out) {
    extern __shared__ float sm[];
    float* Qs = sm;
    float* Ks = Qs + 64 * 80;
    float* Vs = Ks + 77 * 80;
    float* Ss = Vs + 77 * 80;
    float* lrow = Ss + 64 * 80;

    int bh = blockIdx.y;
    int b = bh >> 3, h = bh & 7;
    int qbase = blockIdx.x * 64;
    const __nv_bfloat16* qp = q   + (size_t)b * NN * DD   + h * DHD;
    const __nv_bfloat16* kp = kvc + (size_t)b * CNN * KVS + h * DHD;
    const __nv_bfloat16* vp = kp + 640;

    int tid = threadIdx.x;
    for (int i = tid; i < 64 * 80; i += 256) {
        int r = i / 80, d = i % 80;
        Qs[i] = __bfloat162float(qp[(size_t)(qbase + r) * DD + d]);
    }
    for (int i = tid; i < 77 * 80; i += 256) {
        int r = i / 80, d = i % 80;
        Ks[i] = __bfloat162float(kp[(size_t)r * KVS + d]);
        Vs[i] = __bfloat162float(vp[(size_t)r * KVS + d]);
    }
    __syncthreads();

    int rr = tid >> 2, cc = tid & 3;
    const float scale = 0.11180339887498949f;

    float mx = -1e30f;
    for (int j = cc; j < CNN; j += 4) {
        const float* qrow = &Qs[rr * 80];
        const float* krow = &Ks[j * 80];
        float s = 0.f;
        #pragma unroll
        for (int d4 = 0; d4 < 20; d4++) {
            float4 a  = *(const float4*)&qrow[d4 * 4];
            float4 kk = *(const float4*)&krow[d4 * 4];
            s += a.x*kk.x + a.y*kk.y + a.z*kk.z + a.w*kk.w;
        }
        s *= scale;
        Ss[rr * 80 + j] = s;
        mx = fmaxf(mx, s);
    }
    mx = fmaxf(mx, __shfl_xor_sync(0xffffffffu, mx, 1));
    mx = fmaxf(mx, __shfl_xor_sync(0xffffffffu, mx, 2));
    float sum = 0.f;
    for (int j = cc; j < CNN; j += 4) {
        float p = __expf(Ss[rr * 80 + j] - mx);
        Ss[rr * 80 + j] = p;
        sum += p;
    }
    sum += __shfl_xor_sync(0xffffffffu, sum, 1);
    sum += __shfl_xor_sync(0xffffffffu, sum, 2);
    if (cc == 0) lrow[rr] = sum;
    __syncwarp();

    float o[20];
    #pragma unroll
    for (int i = 0; i < 20; i++) o[i] = 0.f;
    for (int j = 0; j < CNN; j++) {
        float p = Ss[rr * 80 + j];
        const float* vrow = &Vs[j * 80 + cc * 20];
        #pragma unroll
        for (int i4 = 0; i4 < 5; i4++) {
            float4 vv = *(const float4*)&vrow[i4 * 4];
            o[i4*4+0] += p * vv.x;
            o[i4*4+1] += p * vv.y;
            o[i4*4+2] += p * vv.z;
            o[i4*4+3] += p * vv.w;
        }
    }
    float inv = 1.0f / lrow[rr];
    __nv_bfloat16* op = out + (size_t)b * NN * DD + h * DHD
                            + (size_t)(qbase + rr) * DD + cc * 20;
    #pragma unroll
    for (int i2 = 0; i2 < 10; i2++) {
        *(uint32_t*)(op + i2 * 2) = packbf2(o[i2*2+0] * inv, o[i2*2+1] * inv);
    }
}

// ================= launch =================
extern "C" void kernel_launch(void* const* d_in, const int* in_sizes, int n_in,
                              void* d_out, int out_size) {
    const float* x       = (const float*)d_in[0];
    const float* context = (const float*)d_in[1];
    const float* ln1_w = (const float*)d_in[2];
    const float* ln1_b = (const float*)d_in[3];
    const float* ln2_w = (const float*)d_in[4];
    const float* ln2_b = (const float*)d_in[5];
    const float* ln3_w = (const float*)d_in[6];
    const float* ln3_b = (const float*)d_in[7];
    const float* wq1 = (const float*)d_in[8];
    const float* wk1 = (const float*)d_in[9];
    const float* wv1 = (const float*)d_in[10];
    const float* wo1 = (const float*)d_in[11];
    const float* bo1 = (const float*)d_in[12];
    const float* wq2 = (const float*)d_in[13];
    const float* wk2 = (const float*)d_in[14];
    const float* wv2 = (const float*)d_in[15];
    const float* wo2 = (const float*)d_in[16];
    const float* bo2 = (const float*)d_in[17];
    const float* w_ff1 = (const float*)d_in[18];
    const float* b_ff1 = (const float*)d_in[19];
    const float* w_ff2 = (const float*)d_in[20];
    const float* b_ff2 = (const float*)d_in[21];
    float* out = (float*)d_out;

    float *x1, *x2;
    __nv_bfloat16 *hbf, *qkvbf, *qbf, *attnbf, *ffbf, *ctxbf, *kvcbf;
    __nv_bfloat16 *wqkvt, *wo1t, *wq2t, *wkv2t, *wo2t, *wff1t, *wff2t;
    cudaGetSymbolAddress((void**)&x1, g_x1);
    cudaGetSymbolAddress((void**)&x2, g_x2);
    cudaGetSymbolAddress((void**)&hbf, g_hbf);
    cudaGetSymbolAddress((void**)&qkvbf, g_qkvbf);
    cudaGetSymbolAddress((void**)&qbf, g_qbf);
    cudaGetSymbolAddress((void**)&attnbf, g_attnbf);
    cudaGetSymbolAddress((void**)&ffbf, g_ffbf);
    cudaGetSymbolAddress((void**)&ctxbf, g_ctxbf);
    cudaGetSymbolAddress((void**)&kvcbf, g_kvcbf);
    cudaGetSymbolAddress((void**)&wqkvt, g_wqkvt);
    cudaGetSymbolAddress((void**)&wo1t, g_wo1t);
    cudaGetSymbolAddress((void**)&wq2t, g_wq2t);
    cudaGetSymbolAddress((void**)&wkv2t, g_wkv2t);
    cudaGetSymbolAddress((void**)&wo2t, g_wo2t);
    cudaGetSymbolAddress((void**)&wff1t, g_wff1t);
    cudaGetSymbolAddress((void**)&wff2t, g_wff2t);

    cudaFuncSetAttribute(hmma_gemm<0,0,1>,  cudaFuncAttributeMaxDynamicSharedMemorySize, GEMM_DSMEM);
    cudaFuncSetAttribute(hmma_gemm<1,1,0>,  cudaFuncAttributeMaxDynamicSharedMemorySize, GEMM_DSMEM);
    cudaFuncSetAttribute(hmma_gemm<1,0,2>,  cudaFuncAttributeMaxDynamicSharedMemorySize, GEMM_DSMEM);
    cudaFuncSetAttribute(self_attn_hmma,    cudaFuncAttributeMaxDynamicSharedMemorySize, ATT_SMEM);
    cudaFuncSetAttribute(cross_attn_kernel, cudaFuncAttributeMaxDynamicSharedMemorySize, CA_SMEM);

    dim3 tb(32, 32);
    wtrans_kernel<<<dim3(DD/32, DD/32), tb>>>(wq1, wqkvt, DD, DD);
    wtrans_kernel<<<dim3(DD/32, DD/32), tb>>>(wk1, wqkvt + DD*DD, DD, DD);
    wtrans_kernel<<<dim3(DD/32, DD/32), tb>>>(wv1, wqkvt + 2*DD*DD, DD, DD);
    wtrans_kernel<<<dim3(DD/32, DD/32), tb>>>(wo1, wo1t, DD, DD);
    wtrans_kernel<<<dim3(DD/32, DD/32), tb>>>(wq2, wq2t, DD, DD);
    wtrans_kernel<<<dim3(DD/32, CDD/32), tb>>>(wk2, wkv2t, CDD, DD);
    wtrans_kernel<<<dim3(DD/32, CDD/32), tb>>>(wv2, wkv2t + DD*CDD, CDD, DD);
    wtrans_kernel<<<dim3(DD/32, DD/32), tb>>>(wo2, wo2t, DD, DD);
    wtrans_kernel<<<dim3(2*FFF/32, DD/32), tb>>>(w_ff1, wff1t, DD, 2*FFF);
    wtrans_kernel<<<dim3(DD/32, FFF/32), tb>>>(w_ff2, wff2t, FFF, DD);
    f2b_kernel<<<(CROWS*CDD/4 + 255)/256, 256>>>(context, ctxbf, CROWS*CDD/4);

    dim3 gqkv(QKVS/128, ROWS/128);          // (15, 64)
    dim3 g640(DD/128, ROWS/128);            // (5, 64)
    dim3 gff1(FFF/64, ROWS/128);            // (40, 64)
    dim3 gkvc(KVS/128, (CROWS + 127)/128);  // (10, 2)
    dim3 gattn(NN/128, BB*HH);              // (32, 16)  self-attn 128-q tiles
    dim3 gca(NN/64, BB*HH);                 // (64, 16)  cross-attn 64-q tiles

    // ----- self-attention block -----
    ln_kernel<<<ROWS, 160>>>(x, ln1_w, ln1_b, hbf);
    hmma_gemm<0,0,1><<<gqkv, 256, GEMM_DSMEM>>>(hbf, wqkvt, nullptr, nullptr, qkvbf, ROWS, QKVS, DD);
    self_attn_hmma<<<gattn, 256, ATT_SMEM>>>(qkvbf, attnbf);
    hmma_gemm<1,1,0><<<g640, 256, GEMM_DSMEM>>>(attnbf, wo1t, bo1, x, x1, ROWS, DD, DD);

    // ----- cross-attention block -----
    ln_kernel<<<ROWS, 160>>>(x1, ln2_w, ln2_b, hbf);
    hmma_gemm<0,0,1><<<g640, 256, GEMM_DSMEM>>>(hbf, wq2t, nullptr, nullptr, qbf, ROWS, DD, DD);
    hmma_gemm<0,0,1><<<gkvc, 256, GEMM_DSMEM>>>(ctxbf, wkv2t, nullptr, nullptr, kvcbf, CROWS, KVS, CDD);
    cross_attn_kernel<<<gca, 256, CA_SMEM>>>(qbf, kvcbf, attnbf);
    hmma_gemm<1,1,0><<<g640, 256, GEMM_DSMEM>>>(attnbf, wo2t, bo2, x1, x2, ROWS, DD, DD);

    // ----- GEGLU FF block (geglu fused into FF1 epilogue) -----
    ln_kernel<<<ROWS, 160>>>(x2, ln3_w, ln3_b, hbf);
    hmma_gemm<1,0,2><<<gff1, 256, GEMM_DSMEM>>>(hbf, wff1t, b_ff1, nullptr, ffbf, ROWS, FFF, DD);
    hmma_gemm<1,1,0><<<g640, 256, GEMM_DSMEM>>>(ffbf, wff2t, b_ff2, x2, out, ROWS, DD, FFF);
}